// round 1
// baseline (speedup 1.0000x reference)
#include <cuda_runtime.h>
#include <cstdint>
#include <math.h>

// Problem dims (fixed by the dataset)
#define T_TOK 8192          // B*S = 4*2048
#define HID   2048          // hidden size H
#define IMD   8192          // intermediate I
#define N1    16384         // 2*I

// ---------------- scratch (device globals; no allocation allowed) -------------
__device__ int8_t g_wgq[(size_t)N1 * HID];       // quantized w_gate  (33.5MB)
__device__ int8_t g_wdq[(size_t)HID * IMD];      // quantized w_down  (16.8MB)
__device__ int8_t g_xq [(size_t)T_TOK * HID];    // quantized x       (16.8MB)
__device__ int8_t g_hq [(size_t)T_TOK * IMD];    // quantized hidden  (67MB)
__device__ float  g_xds[T_TOK];                  // per-token dequant scale for x
__device__ float  g_hds[T_TOK];                  // per-token dequant scale for h
__device__ float  g_y  [(size_t)T_TOK * N1];     // GEMM1 output (512MB)
__device__ double g_part[4096];                  // reduction partials
__device__ float  g_sg[2];                       // w_gate: [0]=wscale, [1]=1/wscale
__device__ float  g_sd[2];                       // w_down: [0]=wscale, [1]=1/wscale

// ---------------- weight abs-mean (deterministic two-stage, double accum) -----
__global__ void k_absum_partial(const float* __restrict__ w, double* __restrict__ part) {
    __shared__ double sm[256];
    const size_t base = (size_t)blockIdx.x * 16384;           // 16384 floats per block
    const float4* w4 = (const float4*)(w + base);
    double s = 0.0;
    for (int i = threadIdx.x; i < 4096; i += 256) {
        float4 v = w4[i];
        s += (double)fabsf(v.x) + (double)fabsf(v.y) + (double)fabsf(v.z) + (double)fabsf(v.w);
    }
    sm[threadIdx.x] = s; __syncthreads();
    for (int o = 128; o > 0; o >>= 1) {
        if (threadIdx.x < o) sm[threadIdx.x] += sm[threadIdx.x + o];
        __syncthreads();
    }
    if (threadIdx.x == 0) part[blockIdx.x] = sm[0];
}

__global__ void k_absum_final(const double* __restrict__ part, int G, double inv_n,
                              float* __restrict__ out2) {
    __shared__ double sm[256];
    double s = 0.0;
    for (int i = threadIdx.x; i < G; i += 256) s += part[i];
    sm[threadIdx.x] = s; __syncthreads();
    for (int o = 128; o > 0; o >>= 1) {
        if (threadIdx.x < o) sm[threadIdx.x] += sm[threadIdx.x + o];
        __syncthreads();
    }
    if (threadIdx.x == 0) {
        float mean = (float)(sm[0] * inv_n);
        float wm = fmaxf(mean, 1e-5f);           // clip(mean, Q_EPS)
        float ws = __fdiv_rn(1.0f, wm);          // weight scale (matches 1/clip)
        out2[0] = ws;
        out2[1] = __fdiv_rn(1.0f, ws);           // dequant factor 1/scale
    }
}

// ---------------- ternary weight quantization ---------------------------------
__global__ void k_quant_w(const float4* __restrict__ w, char4* __restrict__ q,
                          const float* __restrict__ st, int n4) {
    int i = blockIdx.x * 256 + threadIdx.x;
    if (i >= n4) return;
    const float ws = st[0];
    float4 v = w[i];
    char4 o;
    o.x = (signed char)fminf(fmaxf(rintf(v.x * ws), -1.f), 1.f);
    o.y = (signed char)fminf(fmaxf(rintf(v.y * ws), -1.f), 1.f);
    o.z = (signed char)fminf(fmaxf(rintf(v.z * ws), -1.f), 1.f);
    o.w = (signed char)fminf(fmaxf(rintf(v.w * ws), -1.f), 1.f);
    q[i] = o;
}

// refined rsqrt (full fp32 precision, robust against --use_fast_math)
__device__ __forceinline__ float rsqrt_acc(float v) {
    float r = rsqrtf(v);
    r = r * (1.5f - 0.5f * v * r * r);
    return r;
}

// ---------------- RMSNorm + per-token int8 quant of x -------------------------
__global__ void k_rq_x(const float* __restrict__ X, int8_t* __restrict__ Q,
                       float* __restrict__ dsd) {
    const int row = blockIdx.x;
    const int tid = threadIdx.x;
    const float* xr = X + (size_t)row * HID;
    __shared__ float s1[256], s2[256];
    float ss = 0.f, am = 0.f;
    float xv[8];
#pragma unroll
    for (int k = 0; k < 8; k++) {
        float v = xr[tid + k * 256];
        xv[k] = v;
        ss += v * v;
        am = fmaxf(am, fabsf(v));
    }
    s1[tid] = ss; s2[tid] = am; __syncthreads();
    for (int o = 128; o > 0; o >>= 1) {
        if (tid < o) { s1[tid] += s1[tid + o]; s2[tid] = fmaxf(s2[tid], s2[tid + o]); }
        __syncthreads();
    }
    const float ms = s1[0] * (1.0f / HID) + 1e-8f;
    const float r  = rsqrt_acc(ms);
    const float c  = fmaxf(s2[0] * r, 1e-5f);    // clip(max|xn|, Q_EPS)
    const float sc = __fdiv_rn(127.0f, c);
    int8_t* qr = Q + (size_t)row * HID;
#pragma unroll
    for (int k = 0; k < 8; k++) {
        float xn = xv[k] * r;
        float qv = fminf(fmaxf(rintf(xn * sc), -128.f), 127.f);
        qr[tid + k * 256] = (int8_t)qv;
    }
    if (tid == 0) dsd[row] = __fdiv_rn(1.0f, sc);
}

// ---------------- fused SiLU(gate)*v + RMSNorm + quant -------------------------
__global__ void k_silu_rq(const float* __restrict__ Y, int8_t* __restrict__ Q,
                          float* __restrict__ dsd) {
    const int row = blockIdx.x;
    const int tid = threadIdx.x;
    const float* gp = Y + (size_t)row * N1;
    const float* vp = gp + IMD;
    __shared__ float h[IMD];
    __shared__ float s1[256], s2[256];
    float ss = 0.f, am = 0.f;
    for (int j = tid; j < IMD; j += 256) {
        float g = gp[j], v = vp[j];
        float sig = __fdiv_rn(1.0f, 1.0f + expf(-g));
        float hv = (g * sig) * v;
        h[j] = hv;
        ss += hv * hv;
        am = fmaxf(am, fabsf(hv));
    }
    s1[tid] = ss; s2[tid] = am; __syncthreads();
    for (int o = 128; o > 0; o >>= 1) {
        if (tid < o) { s1[tid] += s1[tid + o]; s2[tid] = fmaxf(s2[tid], s2[tid + o]); }
        __syncthreads();
    }
    const float ms = s1[0] * (1.0f / IMD) + 1e-8f;
    const float r  = rsqrt_acc(ms);
    const float c  = fmaxf(s2[0] * r, 1e-5f);
    const float sc = __fdiv_rn(127.0f, c);
    int8_t* qr = Q + (size_t)row * IMD;
    for (int j = tid; j < IMD; j += 256) {
        float xn = h[j] * r;
        float qv = fminf(fmaxf(rintf(xn * sc), -128.f), 127.f);
        qr[j] = (int8_t)qv;
    }
    if (tid == 0) dsd[row] = __fdiv_rn(1.0f, sc);
}

// ---------------- int8 GEMM (dp4a): C[M,N] = (A[M,K] . B[N,K]^T) * rds[m]*wst[1]
__global__ void __launch_bounds__(256, 2)
k_gemm_s8(const int8_t* __restrict__ A, const int8_t* __restrict__ B,
          float* __restrict__ C, const float* __restrict__ rds,
          const float* __restrict__ wst, int M, int N, int K) {
    __shared__ int aS[16][128];      // [k4][m] : 4 consecutive k bytes packed per int
    __shared__ int bS[16][128];      // [k4][n]
    const int tid = threadIdx.x;
    const int tx = tid & 15;         // output col group
    const int ty = tid >> 4;         // output row group
    const int lr = tid >> 2;         // loader row (0..63)
    const int lc = tid & 3;          // loader 16B chunk in K (0..3)
    const int rowA = blockIdx.y << 7;
    const int rowB = blockIdx.x << 7;

    const int8_t* Ap = A + (size_t)(rowA + lr) * K + (lc << 4);
    const int8_t* Bp = B + (size_t)(rowB + lr) * K + (lc << 4);
    const size_t s64 = (size_t)64 * K;

    int acc[8][8];
#pragma unroll
    for (int i = 0; i < 8; i++)
#pragma unroll
        for (int j = 0; j < 8; j++) acc[i][j] = 0;

    for (int kt = 0; kt < K; kt += 64) {
        int4 a0 = *(const int4*)(Ap + kt);
        int4 a1 = *(const int4*)(Ap + s64 + kt);
        int4 b0 = *(const int4*)(Bp + kt);
        int4 b1 = *(const int4*)(Bp + s64 + kt);
        __syncthreads();
        const int kb = lc << 2;
        aS[kb + 0][lr] = a0.x; aS[kb + 1][lr] = a0.y; aS[kb + 2][lr] = a0.z; aS[kb + 3][lr] = a0.w;
        aS[kb + 0][lr + 64] = a1.x; aS[kb + 1][lr + 64] = a1.y; aS[kb + 2][lr + 64] = a1.z; aS[kb + 3][lr + 64] = a1.w;
        bS[kb + 0][lr] = b0.x; bS[kb + 1][lr] = b0.y; bS[kb + 2][lr] = b0.z; bS[kb + 3][lr] = b0.w;
        bS[kb + 0][lr + 64] = b1.x; bS[kb + 1][lr + 64] = b1.y; bS[kb + 2][lr + 64] = b1.z; bS[kb + 3][lr + 64] = b1.w;
        __syncthreads();
#pragma unroll
        for (int k4 = 0; k4 < 16; k4++) {
            int4 af0 = *(const int4*)&aS[k4][ty << 2];
            int4 af1 = *(const int4*)&aS[k4][(ty << 2) + 64];
            int4 bf0 = *(const int4*)&bS[k4][tx << 2];
            int4 bf1 = *(const int4*)&bS[k4][(tx << 2) + 64];
            int av[8] = {af0.x, af0.y, af0.z, af0.w, af1.x, af1.y, af1.z, af1.w};
            int bv[8] = {bf0.x, bf0.y, bf0.z, bf0.w, bf1.x, bf1.y, bf1.z, bf1.w};
#pragma unroll
            for (int i = 0; i < 8; i++)
#pragma unroll
                for (int j = 0; j < 8; j++)
                    acc[i][j] = __dp4a(av[i], bv[j], acc[i][j]);
        }
    }

    const float wv = wst[1];
#pragma unroll
    for (int i = 0; i < 8; i++) {
        const int m = rowA + (ty << 2) + ((i < 4) ? i : 60 + i);
        const float ds = rds[m] * wv;
        float* cr = C + (size_t)m * N + rowB + (tx << 2);
#pragma unroll
        for (int j = 0; j < 8; j++) {
            cr[(j < 4) ? j : 60 + j] = (float)acc[i][j] * ds;
        }
    }
}

// ---------------- launch ------------------------------------------------------
extern "C" void kernel_launch(void* const* d_in, const int* in_sizes, int n_in,
                              void* d_out, int out_size) {
    const float* x  = (const float*)d_in[0];   // [4,2048,2048]
    const float* wg = (const float*)d_in[1];   // [16384,2048]
    const float* wd = (const float*)d_in[2];   // [2048,8192]
    float* out = (float*)d_out;                // [4,2048,2048]

    void *p_wgq, *p_wdq, *p_xq, *p_hq, *p_xds, *p_hds, *p_y, *p_part, *p_sg, *p_sd;
    cudaGetSymbolAddress(&p_wgq, g_wgq);
    cudaGetSymbolAddress(&p_wdq, g_wdq);
    cudaGetSymbolAddress(&p_xq,  g_xq);
    cudaGetSymbolAddress(&p_hq,  g_hq);
    cudaGetSymbolAddress(&p_xds, g_xds);
    cudaGetSymbolAddress(&p_hds, g_hds);
    cudaGetSymbolAddress(&p_y,   g_y);
    cudaGetSymbolAddress(&p_part, g_part);
    cudaGetSymbolAddress(&p_sg,  g_sg);
    cudaGetSymbolAddress(&p_sd,  g_sd);

    // 1) weight scales (deterministic)
    k_absum_partial<<<2048, 256>>>(wg, (double*)p_part);
    k_absum_final<<<1, 256>>>((const double*)p_part, 2048, 1.0 / 33554432.0, (float*)p_sg);
    k_absum_partial<<<1024, 256>>>(wd, (double*)p_part);
    k_absum_final<<<1, 256>>>((const double*)p_part, 1024, 1.0 / 16777216.0, (float*)p_sd);

    // 2) quantize weights to ternary int8
    k_quant_w<<<(33554432 / 4 + 255) / 256, 256>>>((const float4*)wg, (char4*)p_wgq,
                                                   (const float*)p_sg, 33554432 / 4);
    k_quant_w<<<(16777216 / 4 + 255) / 256, 256>>>((const float4*)wd, (char4*)p_wdq,
                                                   (const float*)p_sd, 16777216 / 4);

    // 3) RMSNorm + quantize x
    k_rq_x<<<T_TOK, 256>>>(x, (int8_t*)p_xq, (float*)p_xds);

    // 4) GEMM1: y[8192,16384] = xq . wgq^T  (int32 accum, fused dequant)
    k_gemm_s8<<<dim3(N1 / 128, T_TOK / 128), 256>>>(
        (const int8_t*)p_xq, (const int8_t*)p_wgq, (float*)p_y,
        (const float*)p_xds, (const float*)p_sg, T_TOK, N1, HID);

    // 5) SiLU(gate)*v + RMSNorm + quantize
    k_silu_rq<<<T_TOK, 256>>>((const float*)p_y, (int8_t*)p_hq, (float*)p_hds);

    // 6) GEMM2: out[8192,2048] = hq . wdq^T
    k_gemm_s8<<<dim3(HID / 128, T_TOK / 128), 256>>>(
        (const int8_t*)p_hq, (const int8_t*)p_wdq, out,
        (const float*)p_hds, (const float*)p_sd, T_TOK, HID, IMD);
}

// round 3
// speedup vs baseline: 1.1328x; 1.1328x over previous
#include <cuda_runtime.h>
#include <cstdint>
#include <math.h>

// Problem dims (fixed)
#define T_TOK 8192          // B*S
#define HID   2048
#define IMD   8192
#define N1    16384         // 2*IMD

// ---------------- scratch ------------------------------------------------------
__device__ int8_t g_wgq[(size_t)N1 * HID];     // quantized w_gate, row-interleaved (g,v)
__device__ int8_t g_wdq[(size_t)HID * IMD];    // quantized w_down
__device__ int8_t g_xq [(size_t)T_TOK * HID];
__device__ int8_t g_hq [(size_t)T_TOK * IMD];
__device__ float  g_xds[T_TOK];
__device__ float  g_hds[T_TOK];
__device__ float  g_h  [(size_t)T_TOK * IMD];  // silu(g)*v (fp32)
__device__ double g_part[4096];
__device__ float  g_sg[2];
__device__ float  g_sd[2];

// ---------------- PTX helpers ---------------------------------------------------
__device__ __forceinline__ uint32_t s2u(const void* p) {
    uint32_t a;
    asm("{ .reg .u64 t; cvta.to.shared.u64 t, %1; cvt.u32.u64 %0, t; }" : "=r"(a) : "l"(p));
    return a;
}

__device__ __forceinline__ void cp16(uint32_t s, const void* g) {
    asm volatile("cp.async.cg.shared.global [%0], [%1], 16;" :: "r"(s), "l"(g));
}

__device__ __forceinline__ void ldsm4(uint32_t* r, uint32_t addr) {
    asm volatile("ldmatrix.sync.aligned.m8n8.x4.shared.b16 {%0,%1,%2,%3}, [%4];"
        : "=r"(r[0]), "=r"(r[1]), "=r"(r[2]), "=r"(r[3]) : "r"(addr));
}
__device__ __forceinline__ void ldsm2(uint32_t* r, uint32_t addr) {
    asm volatile("ldmatrix.sync.aligned.m8n8.x2.shared.b16 {%0,%1}, [%2];"
        : "=r"(r[0]), "=r"(r[1]) : "r"(addr));
}
__device__ __forceinline__ void mma_s8(int* d, const uint32_t* a, const uint32_t* b) {
    asm volatile("mma.sync.aligned.m16n8k32.row.col.s32.s8.s8.s32 "
        "{%0,%1,%2,%3}, {%4,%5,%6,%7}, {%8,%9}, {%0,%1,%2,%3};"
        : "+r"(d[0]), "+r"(d[1]), "+r"(d[2]), "+r"(d[3])
        : "r"(a[0]), "r"(a[1]), "r"(a[2]), "r"(a[3]), "r"(b[0]), "r"(b[1]));
}

// smem tile: [128 rows][64 bytes], 16B chunk swizzle: chunk ^= (row>>1)&3
__device__ __forceinline__ uint32_t smaddr(uint32_t base, int row, int chunk) {
    return base + row * 64 + ((chunk ^ ((row >> 1) & 3)) << 4);
}

// ---------------- weight abs-mean (deterministic) ---------------------------------
__global__ void k_absum_partial(const float* __restrict__ w, double* __restrict__ part) {
    __shared__ double sm[256];
    const size_t base = (size_t)blockIdx.x * 16384;
    const float4* w4 = (const float4*)(w + base);
    double s = 0.0;
    for (int i = threadIdx.x; i < 4096; i += 256) {
        float4 v = w4[i];
        s += (double)fabsf(v.x) + (double)fabsf(v.y) + (double)fabsf(v.z) + (double)fabsf(v.w);
    }
    sm[threadIdx.x] = s; __syncthreads();
    for (int o = 128; o > 0; o >>= 1) {
        if (threadIdx.x < o) sm[threadIdx.x] += sm[threadIdx.x + o];
        __syncthreads();
    }
    if (threadIdx.x == 0) part[blockIdx.x] = sm[0];
}

__global__ void k_absum_final(const double* __restrict__ part, int G, double inv_n,
                              float* __restrict__ out2) {
    __shared__ double sm[256];
    double s = 0.0;
    for (int i = threadIdx.x; i < G; i += 256) s += part[i];
    sm[threadIdx.x] = s; __syncthreads();
    for (int o = 128; o > 0; o >>= 1) {
        if (threadIdx.x < o) sm[threadIdx.x] += sm[threadIdx.x + o];
        __syncthreads();
    }
    if (threadIdx.x == 0) {
        float mean = (float)(sm[0] * inv_n);
        float wm = fmaxf(mean, 1e-5f);
        float ws = __fdiv_rn(1.0f, wm);
        out2[0] = ws;
        out2[1] = __fdiv_rn(1.0f, ws);
    }
}

// ---------------- weight quant ----------------------------------------------------
__global__ void k_quant_w(const float4* __restrict__ w, char4* __restrict__ q,
                          const float* __restrict__ st, int n4) {
    int i = blockIdx.x * 256 + threadIdx.x;
    if (i >= n4) return;
    const float ws = st[0];
    float4 v = w[i];
    char4 o;
    o.x = (signed char)fminf(fmaxf(rintf(v.x * ws), -1.f), 1.f);
    o.y = (signed char)fminf(fmaxf(rintf(v.y * ws), -1.f), 1.f);
    o.z = (signed char)fminf(fmaxf(rintf(v.z * ws), -1.f), 1.f);
    o.w = (signed char)fminf(fmaxf(rintf(v.w * ws), -1.f), 1.f);
    q[i] = o;
}

// gate/v row interleave: output row = (o<I) ? 2o : 2(o-I)+1
__global__ void k_quant_wg(const float4* __restrict__ w, char4* __restrict__ q,
                           const float* __restrict__ st, int n4) {
    int i = blockIdx.x * 256 + threadIdx.x;
    if (i >= n4) return;
    const float ws = st[0];
    float4 v = w[i];
    char4 o;
    o.x = (signed char)fminf(fmaxf(rintf(v.x * ws), -1.f), 1.f);
    o.y = (signed char)fminf(fmaxf(rintf(v.y * ws), -1.f), 1.f);
    o.z = (signed char)fminf(fmaxf(rintf(v.z * ws), -1.f), 1.f);
    o.w = (signed char)fminf(fmaxf(rintf(v.w * ws), -1.f), 1.f);
    const int rl4 = HID / 4;
    int orow = i / rl4, c = i - orow * rl4;
    int r = (orow < IMD) ? (orow << 1) : (((orow - IMD) << 1) + 1);
    q[(size_t)r * rl4 + c] = o;
}

__device__ __forceinline__ float rsqrt_acc(float v) {
    float r = rsqrtf(v);
    return r * (1.5f - 0.5f * v * r * r);
}

// ---------------- RMSNorm + quant (x, H=2048) -------------------------------------
__global__ void k_rq_x(const float* __restrict__ X, int8_t* __restrict__ Q,
                       float* __restrict__ dsd) {
    const int row = blockIdx.x, tid = threadIdx.x;
    const float* xr = X + (size_t)row * HID;
    __shared__ float s1[256], s2[256];
    float ss = 0.f, am = 0.f, xv[8];
#pragma unroll
    for (int k = 0; k < 8; k++) {
        float v = xr[tid + k * 256];
        xv[k] = v; ss += v * v; am = fmaxf(am, fabsf(v));
    }
    s1[tid] = ss; s2[tid] = am; __syncthreads();
    for (int o = 128; o > 0; o >>= 1) {
        if (tid < o) { s1[tid] += s1[tid + o]; s2[tid] = fmaxf(s2[tid], s2[tid + o]); }
        __syncthreads();
    }
    const float r  = rsqrt_acc(s1[0] * (1.0f / HID) + 1e-8f);
    const float sc = __fdiv_rn(127.0f, fmaxf(s2[0] * r, 1e-5f));
    int8_t* qr = Q + (size_t)row * HID;
#pragma unroll
    for (int k = 0; k < 8; k++)
        qr[tid + k * 256] = (int8_t)fminf(fmaxf(rintf(xv[k] * r * sc), -128.f), 127.f);
    if (tid == 0) dsd[row] = __fdiv_rn(1.0f, sc);
}

// ---------------- RMSNorm + quant (h, I=8192) --------------------------------------
__global__ void k_rq_h(const float* __restrict__ X, int8_t* __restrict__ Q,
                       float* __restrict__ dsd) {
    const int row = blockIdx.x, tid = threadIdx.x;
    const float* xr = X + (size_t)row * IMD;
    __shared__ float s1[256], s2[256];
    float ss = 0.f, am = 0.f, xv[32];
#pragma unroll
    for (int k = 0; k < 32; k++) {
        float v = xr[tid + k * 256];
        xv[k] = v; ss += v * v; am = fmaxf(am, fabsf(v));
    }
    s1[tid] = ss; s2[tid] = am; __syncthreads();
    for (int o = 128; o > 0; o >>= 1) {
        if (tid < o) { s1[tid] += s1[tid + o]; s2[tid] = fmaxf(s2[tid], s2[tid + o]); }
        __syncthreads();
    }
    const float r  = rsqrt_acc(s1[0] * (1.0f / IMD) + 1e-8f);
    const float sc = __fdiv_rn(127.0f, fmaxf(s2[0] * r, 1e-5f));
    int8_t* qr = Q + (size_t)row * IMD;
#pragma unroll
    for (int k = 0; k < 32; k++)
        qr[tid + k * 256] = (int8_t)fminf(fmaxf(rintf(xv[k] * r * sc), -128.f), 127.f);
    if (tid == 0) dsd[row] = __fdiv_rn(1.0f, sc);
}

// ---------------- int8 IMMA GEMM ----------------------------------------------------
// C[M,N] CTA tile 128x128, K-tile 64, 8 warps (2x4), warp tile 64x32.
// mma.m16n8k32 s8. 4-stage cp.async pipeline, 16KB/stage.
// GATED: B rows interleaved (gate,v) -> epilogue emits silu(g)*v, output width N/2.
static const int GSMEM = 65536;

template<bool GATED>
__global__ void __launch_bounds__(256, 2)
k_gemm_imma(const int8_t* __restrict__ A, const int8_t* __restrict__ B,
            float* __restrict__ C, const float* __restrict__ rds,
            const float* __restrict__ wst, int K, int ldC) {
    extern __shared__ char dsm[];
    const uint32_t base = s2u(dsm);
    const int tid  = threadIdx.x;
    const int lane = tid & 31;
    const int warp = tid >> 5;
    const int wm = warp >> 2;          // 0..1  (rows, 64 each)
    const int wn = warp & 3;           // 0..3  (cols, 32 each)
    const int rowA = blockIdx.y << 7;
    const int rowB = blockIdx.x << 7;
    const int KT = K >> 6;

    // loader mapping: 2x16B for A, 2x16B for B per thread per stage
    const int lrow = tid >> 1;               // 0..127
    const int lcb  = (tid & 1) << 1;         // chunk base 0 or 2
    const int8_t* gA = A + (size_t)(rowA + lrow) * K + (lcb << 4);
    const int8_t* gB = B + (size_t)(rowB + lrow) * K + (lcb << 4);
    const uint32_t sA0 = smaddr(base, lrow, lcb);
    const uint32_t sA1 = smaddr(base, lrow, lcb + 1);
    const uint32_t sB0 = smaddr(base + 8192, lrow, lcb);
    const uint32_t sB1 = smaddr(base + 8192, lrow, lcb + 1);

#define LD_STAGE(j) do { \
    const uint32_t off = ((j) & 3) * 16384; \
    const int kt = (j) << 6; \
    cp16(sA0 + off, gA + kt); cp16(sA1 + off, gA + kt + 16); \
    cp16(sB0 + off, gB + kt); cp16(sB1 + off, gB + kt + 16); \
} while (0)

    int acc[4][4][4];
#pragma unroll
    for (int i = 0; i < 4; i++)
#pragma unroll
        for (int j = 0; j < 4; j++)
#pragma unroll
            for (int k = 0; k < 4; k++) acc[i][j][k] = 0;

    LD_STAGE(0); asm volatile("cp.async.commit_group;");
    LD_STAGE(1); asm volatile("cp.async.commit_group;");
    LD_STAGE(2); asm volatile("cp.async.commit_group;");

    // precomputed ldmatrix address components
    const int arow = (lane & 15);        // + wm*64 + ms*16
    const int achk = lane >> 4;          // + ks*2
    const int brow = (lane & 7);         // + wn*32 + ns*8
    const int bchk = (lane >> 3) & 1;    // + ks*2

    for (int j = 0; j < KT; j++) {
        asm volatile("cp.async.wait_group 2;");
        __syncthreads();
        if (j + 3 < KT) LD_STAGE(j + 3);
        asm volatile("cp.async.commit_group;");

        const uint32_t aB = base + (j & 3) * 16384;
        const uint32_t bB = aB + 8192;
#pragma unroll
        for (int ks = 0; ks < 2; ks++) {
            uint32_t bfr[4][2];
#pragma unroll
            for (int ns = 0; ns < 4; ns++)
                ldsm2(bfr[ns], smaddr(bB, wn * 32 + ns * 8 + brow, ks * 2 + bchk));
#pragma unroll
            for (int ms = 0; ms < 4; ms++) {
                uint32_t afr[4];
                ldsm4(afr, smaddr(aB, wm * 64 + ms * 16 + arow, ks * 2 + achk));
#pragma unroll
                for (int ns = 0; ns < 4; ns++)
                    mma_s8(acc[ms][ns], afr, bfr[ns]);
            }
        }
    }

    // ---------------- epilogue (register fragments -> gmem) ----------------
    const float w = wst[1];
#pragma unroll
    for (int ms = 0; ms < 4; ms++) {
        const int r0 = rowA + wm * 64 + ms * 16 + (lane >> 2);
        const float ds0 = rds[r0] * w;
        const float ds1 = rds[r0 + 8] * w;
        if (GATED) {
#pragma unroll
            for (int ns = 0; ns < 4; ns++) {
                const int col = (rowB >> 1) + wn * 16 + ns * 4 + (lane & 3);
                float g0 = (float)acc[ms][ns][0] * ds0;
                float v0 = (float)acc[ms][ns][1] * ds0;
                float g1 = (float)acc[ms][ns][2] * ds1;
                float v1 = (float)acc[ms][ns][3] * ds1;
                C[(size_t)r0 * ldC + col]       = g0 * v0 * __fdiv_rn(1.0f, 1.0f + expf(-g0));
                C[(size_t)(r0 + 8) * ldC + col] = g1 * v1 * __fdiv_rn(1.0f, 1.0f + expf(-g1));
            }
        } else {
#pragma unroll
            for (int ns = 0; ns < 4; ns++) {
                const int col = rowB + wn * 32 + ns * 8 + ((lane & 3) << 1);
                float2 lo = make_float2((float)acc[ms][ns][0] * ds0,
                                        (float)acc[ms][ns][1] * ds0);
                float2 hi = make_float2((float)acc[ms][ns][2] * ds1,
                                        (float)acc[ms][ns][3] * ds1);
                *(float2*)(C + (size_t)r0 * ldC + col)       = lo;
                *(float2*)(C + (size_t)(r0 + 8) * ldC + col) = hi;
            }
        }
    }
}

// ---------------- launch --------------------------------------------------------
extern "C" void kernel_launch(void* const* d_in, const int* in_sizes, int n_in,
                              void* d_out, int out_size) {
    const float* x  = (const float*)d_in[0];
    const float* wg = (const float*)d_in[1];
    const float* wd = (const float*)d_in[2];
    float* out = (float*)d_out;

    void *p_wgq, *p_wdq, *p_xq, *p_hq, *p_xds, *p_hds, *p_h, *p_part, *p_sg, *p_sd;
    cudaGetSymbolAddress(&p_wgq, g_wgq);
    cudaGetSymbolAddress(&p_wdq, g_wdq);
    cudaGetSymbolAddress(&p_xq,  g_xq);
    cudaGetSymbolAddress(&p_hq,  g_hq);
    cudaGetSymbolAddress(&p_xds, g_xds);
    cudaGetSymbolAddress(&p_hds, g_hds);
    cudaGetSymbolAddress(&p_h,   g_h);
    cudaGetSymbolAddress(&p_part, g_part);
    cudaGetSymbolAddress(&p_sg,  g_sg);
    cudaGetSymbolAddress(&p_sd,  g_sd);

    cudaFuncSetAttribute(k_gemm_imma<true>,  cudaFuncAttributeMaxDynamicSharedMemorySize, GSMEM);
    cudaFuncSetAttribute(k_gemm_imma<false>, cudaFuncAttributeMaxDynamicSharedMemorySize, GSMEM);

    // weight scales (deterministic)
    k_absum_partial<<<2048, 256>>>(wg, (double*)p_part);
    k_absum_final<<<1, 256>>>((const double*)p_part, 2048, 1.0 / 33554432.0, (float*)p_sg);
    k_absum_partial<<<1024, 256>>>(wd, (double*)p_part);
    k_absum_final<<<1, 256>>>((const double*)p_part, 1024, 1.0 / 16777216.0, (float*)p_sd);

    // ternary quantize (w_gate row-interleaved)
    k_quant_wg<<<8388608 / 256, 256>>>((const float4*)wg, (char4*)p_wgq, (const float*)p_sg, 8388608);
    k_quant_w <<<4194304 / 256, 256>>>((const float4*)wd, (char4*)p_wdq, (const float*)p_sd, 4194304);

    // RMSNorm + quant x
    k_rq_x<<<T_TOK, 256>>>(x, (int8_t*)p_xq, (float*)p_xds);

    // GEMM1 (gated): h[8192,8192] = silu(g)*v
    k_gemm_imma<true><<<dim3(N1 / 128, T_TOK / 128), 256, GSMEM>>>(
        (const int8_t*)p_xq, (const int8_t*)p_wgq, (float*)p_h,
        (const float*)p_xds, (const float*)p_sg, HID, IMD);

    // RMSNorm + quant h
    k_rq_h<<<T_TOK, 256>>>((const float*)p_h, (int8_t*)p_hq, (float*)p_hds);

    // GEMM2: out[8192,2048]
    k_gemm_imma<false><<<dim3(HID / 128, T_TOK / 128), 256, GSMEM>>>(
        (const int8_t*)p_hq, (const int8_t*)p_wdq, out,
        (const float*)p_hds, (const float*)p_sd, IMD, HID);
}

// round 4
// speedup vs baseline: 1.4578x; 1.2869x over previous
#include <cuda_runtime.h>
#include <cuda_fp16.h>
#include <cstdint>
#include <math.h>

// Problem dims (fixed)
#define T_TOK 8192          // B*S
#define HID   2048
#define IMD   8192
#define N1    16384         // 2*IMD

// ---------------- scratch ------------------------------------------------------
__device__ __half g_wgq[(size_t)N1 * HID];     // quantized w_gate (fp16 ints), (g,v) row-interleaved
__device__ __half g_wdq[(size_t)HID * IMD];    // quantized w_down (fp16 ints)
__device__ __half g_xq [(size_t)T_TOK * HID];  // quantized x (fp16 ints)
__device__ __half g_hq [(size_t)T_TOK * IMD];  // quantized hidden (fp16 ints)
__device__ float  g_xds[T_TOK];
__device__ float  g_hds[T_TOK];
__device__ float  g_h  [(size_t)T_TOK * IMD];  // silu(g)*v (fp32)
__device__ double g_part[4096];
__device__ float  g_sg[2];
__device__ float  g_sd[2];

// ---------------- PTX helpers ---------------------------------------------------
__device__ __forceinline__ uint32_t s2u(const void* p) {
    uint32_t a;
    asm("{ .reg .u64 t; cvta.to.shared.u64 t, %1; cvt.u32.u64 %0, t; }" : "=r"(a) : "l"(p));
    return a;
}

#define SWZ(o) ((o) ^ (((o) >> 3) & 0x70))

__device__ __forceinline__ void cp16(uint32_t s, const void* g) {
    asm volatile("cp.async.cg.shared.global [%0], [%1], 16;" :: "r"(s), "l"(g));
}

__device__ __forceinline__ void ldsm4(uint32_t* r, uint32_t addr) {
    asm volatile("ldmatrix.sync.aligned.m8n8.x4.shared.b16 {%0,%1,%2,%3}, [%4];"
        : "=r"(r[0]), "=r"(r[1]), "=r"(r[2]), "=r"(r[3]) : "r"(addr));
}
__device__ __forceinline__ void ldsm2(uint32_t* r, uint32_t addr) {
    asm volatile("ldmatrix.sync.aligned.m8n8.x2.shared.b16 {%0,%1}, [%2];"
        : "=r"(r[0]), "=r"(r[1]) : "r"(addr));
}
__device__ __forceinline__ void mma_f16(float* d, const uint32_t* a, const uint32_t* b) {
    asm volatile("mma.sync.aligned.m16n8k16.row.col.f32.f16.f16.f32 "
        "{%0,%1,%2,%3}, {%4,%5,%6,%7}, {%8,%9}, {%0,%1,%2,%3};"
        : "+f"(d[0]), "+f"(d[1]), "+f"(d[2]), "+f"(d[3])
        : "r"(a[0]), "r"(a[1]), "r"(a[2]), "r"(a[3]), "r"(b[0]), "r"(b[1]));
}

// ---------------- weight abs-mean (deterministic) ---------------------------------
__global__ void k_absum_partial(const float* __restrict__ w, double* __restrict__ part) {
    __shared__ double sm[256];
    const size_t base = (size_t)blockIdx.x * 16384;
    const float4* w4 = (const float4*)(w + base);
    double s = 0.0;
    for (int i = threadIdx.x; i < 4096; i += 256) {
        float4 v = w4[i];
        s += (double)fabsf(v.x) + (double)fabsf(v.y) + (double)fabsf(v.z) + (double)fabsf(v.w);
    }
    sm[threadIdx.x] = s; __syncthreads();
    for (int o = 128; o > 0; o >>= 1) {
        if (threadIdx.x < o) sm[threadIdx.x] += sm[threadIdx.x + o];
        __syncthreads();
    }
    if (threadIdx.x == 0) part[blockIdx.x] = sm[0];
}

__global__ void k_absum_final(const double* __restrict__ part, int G, double inv_n,
                              float* __restrict__ out2) {
    __shared__ double sm[256];
    double s = 0.0;
    for (int i = threadIdx.x; i < G; i += 256) s += part[i];
    sm[threadIdx.x] = s; __syncthreads();
    for (int o = 128; o > 0; o >>= 1) {
        if (threadIdx.x < o) sm[threadIdx.x] += sm[threadIdx.x + o];
        __syncthreads();
    }
    if (threadIdx.x == 0) {
        float mean = (float)(sm[0] * inv_n);
        float wm = fmaxf(mean, 1e-5f);
        float ws = __fdiv_rn(1.0f, wm);
        out2[0] = ws;
        out2[1] = __fdiv_rn(1.0f, ws);
    }
}

// ---------------- weight quant (ternary, emitted as fp16) --------------------------
__global__ void k_quant_w(const float4* __restrict__ w, __half2* __restrict__ q,
                          const float* __restrict__ st, int n4) {
    int i = blockIdx.x * 256 + threadIdx.x;
    if (i >= n4) return;
    const float ws = st[0];
    float4 v = w[i];
    float a = fminf(fmaxf(rintf(v.x * ws), -1.f), 1.f);
    float b = fminf(fmaxf(rintf(v.y * ws), -1.f), 1.f);
    float c = fminf(fmaxf(rintf(v.z * ws), -1.f), 1.f);
    float d = fminf(fmaxf(rintf(v.w * ws), -1.f), 1.f);
    q[2 * i]     = __floats2half2_rn(a, b);
    q[2 * i + 1] = __floats2half2_rn(c, d);
}

// gate/v row interleave: output row = (o<I) ? 2o : 2(o-I)+1
__global__ void k_quant_wg(const float4* __restrict__ w, __half2* __restrict__ q,
                           const float* __restrict__ st, int n4) {
    int i = blockIdx.x * 256 + threadIdx.x;
    if (i >= n4) return;
    const float ws = st[0];
    float4 v = w[i];
    float a = fminf(fmaxf(rintf(v.x * ws), -1.f), 1.f);
    float b = fminf(fmaxf(rintf(v.y * ws), -1.f), 1.f);
    float c = fminf(fmaxf(rintf(v.z * ws), -1.f), 1.f);
    float d = fminf(fmaxf(rintf(v.w * ws), -1.f), 1.f);
    const int rl4 = HID / 4;
    int orow = i / rl4, ccol = i - orow * rl4;
    int r = (orow < IMD) ? (orow << 1) : (((orow - IMD) << 1) + 1);
    __half2* qr = q + (size_t)r * (HID / 2) + ccol * 2;
    qr[0] = __floats2half2_rn(a, b);
    qr[1] = __floats2half2_rn(c, d);
}

__device__ __forceinline__ float rsqrt_acc(float v) {
    float r = rsqrtf(v);
    return r * (1.5f - 0.5f * v * r * r);
}

// ---------------- RMSNorm + quant (x, H=2048) -------------------------------------
__global__ void k_rq_x(const float* __restrict__ X, __half* __restrict__ Q,
                       float* __restrict__ dsd) {
    const int row = blockIdx.x, tid = threadIdx.x;
    const float* xr = X + (size_t)row * HID;
    __shared__ float s1[256], s2[256];
    float ss = 0.f, am = 0.f, xv[8];
#pragma unroll
    for (int k = 0; k < 8; k++) {
        float v = xr[tid + k * 256];
        xv[k] = v; ss += v * v; am = fmaxf(am, fabsf(v));
    }
    s1[tid] = ss; s2[tid] = am; __syncthreads();
    for (int o = 128; o > 0; o >>= 1) {
        if (tid < o) { s1[tid] += s1[tid + o]; s2[tid] = fmaxf(s2[tid], s2[tid + o]); }
        __syncthreads();
    }
    const float r  = rsqrt_acc(s1[0] * (1.0f / HID) + 1e-8f);
    const float sc = __fdiv_rn(127.0f, fmaxf(s2[0] * r, 1e-5f));
    __half* qr = Q + (size_t)row * HID;
#pragma unroll
    for (int k = 0; k < 8; k++)
        qr[tid + k * 256] = __float2half_rn(fminf(fmaxf(rintf(xv[k] * r * sc), -128.f), 127.f));
    if (tid == 0) dsd[row] = __fdiv_rn(1.0f, sc);
}

// ---------------- RMSNorm + quant (h, I=8192) --------------------------------------
__global__ void k_rq_h(const float* __restrict__ X, __half* __restrict__ Q,
                       float* __restrict__ dsd) {
    const int row = blockIdx.x, tid = threadIdx.x;
    const float* xr = X + (size_t)row * IMD;
    __shared__ float s1[256], s2[256];
    float ss = 0.f, am = 0.f, xv[32];
#pragma unroll
    for (int k = 0; k < 32; k++) {
        float v = xr[tid + k * 256];
        xv[k] = v; ss += v * v; am = fmaxf(am, fabsf(v));
    }
    s1[tid] = ss; s2[tid] = am; __syncthreads();
    for (int o = 128; o > 0; o >>= 1) {
        if (tid < o) { s1[tid] += s1[tid + o]; s2[tid] = fmaxf(s2[tid], s2[tid + o]); }
        __syncthreads();
    }
    const float r  = rsqrt_acc(s1[0] * (1.0f / IMD) + 1e-8f);
    const float sc = __fdiv_rn(127.0f, fmaxf(s2[0] * r, 1e-5f));
    __half* qr = Q + (size_t)row * IMD;
#pragma unroll
    for (int k = 0; k < 32; k++)
        qr[tid + k * 256] = __float2half_rn(fminf(fmaxf(rintf(xv[k] * r * sc), -128.f), 127.f));
    if (tid == 0) dsd[row] = __fdiv_rn(1.0f, sc);
}

// ---------------- fp16 HMMA GEMM (exact integer math) -------------------------------
// C[M,N] CTA tile 128x128, K-tile 64 (128B fp16 rows, SW128), 3-stage cp.async,
// 8 warps (2x4), warp tile 64x32, mma.m16n8k16.f32.f16.f16.f32.
// GATED: B rows interleaved (gate,v) -> epilogue silu(g)*v, output width N/2.
static const int GSMEM = 3 * 32768 + 128;

template<bool GATED>
__global__ void __launch_bounds__(256, 2)
k_gemm_hmma(const __half* __restrict__ A, const __half* __restrict__ B,
            float* __restrict__ C, const float* __restrict__ rds,
            const float* __restrict__ wst, int K, int ldC) {
    extern __shared__ char dsm[];
    const uint32_t base = (s2u(dsm) + 127u) & ~127u;
    const int tid  = threadIdx.x;
    const int lane = tid & 31;
    const int warp = tid >> 5;
    const int wm = warp >> 2;          // 0..1
    const int wn = warp & 3;           // 0..3
    const int rowA = blockIdx.y << 7;
    const int rowB = blockIdx.x << 7;
    const int KT = K >> 6;

    // loader: threads 0..127 -> A rows, 128..255 -> B rows; 8 x 16B per thread
    const int lr = tid & 127;
    const int ab = tid >> 7;
    const char* gsrc = (const char*)((ab ? B : A) + (size_t)((ab ? rowB : rowA) + lr) * K);
    uint32_t dst[8];
#pragma unroll
    for (int c = 0; c < 8; c++)
        dst[c] = base + ab * 16384 + SWZ((uint32_t)(lr * 128 + c * 16));

#define LD_STAGE(j) do { \
    const uint32_t off = ((j) % 3) * 32768; \
    const char* gp = gsrc + (size_t)(j) * 128; \
    _Pragma("unroll") for (int c = 0; c < 8; c++) cp16(dst[c] + off, gp + c * 16); \
} while (0)

    float acc[4][4][4];
#pragma unroll
    for (int i = 0; i < 4; i++)
#pragma unroll
        for (int j = 0; j < 4; j++)
#pragma unroll
            for (int k = 0; k < 4; k++) acc[i][j][k] = 0.f;

    LD_STAGE(0); asm volatile("cp.async.commit_group;");
    LD_STAGE(1); asm volatile("cp.async.commit_group;");

    // ldmatrix per-lane address components
    const int arow = lane & 15;          // + wm*64 + ms*16
    const int achk = lane >> 4;          // + ks*2
    const int brow = lane & 7;           // + wn*32 + ns*8
    const int bchk = (lane >> 3) & 1;    // + ks*2

    for (int j = 0; j < KT; j++) {
        asm volatile("cp.async.wait_group 1;");
        __syncthreads();
        if (j + 2 < KT) LD_STAGE(j + 2);
        asm volatile("cp.async.commit_group;");

        const uint32_t aB = base + (j % 3) * 32768;
        const uint32_t bB = aB + 16384;
#pragma unroll
        for (int ks = 0; ks < 4; ks++) {
            uint32_t bfr[4][2];
#pragma unroll
            for (int ns = 0; ns < 4; ns++)
                bfr[ns][0] = bB + SWZ((uint32_t)((wn * 32 + ns * 8 + brow) * 128 +
                                                 (ks * 2 + bchk) * 16));
#pragma unroll
            for (int ns = 0; ns < 4; ns++)
                ldsm2(bfr[ns], bfr[ns][0]);
#pragma unroll
            for (int ms = 0; ms < 4; ms++) {
                uint32_t afr[4];
                ldsm4(afr, aB + SWZ((uint32_t)((wm * 64 + ms * 16 + arow) * 128 +
                                               (ks * 2 + achk) * 16)));
#pragma unroll
                for (int ns = 0; ns < 4; ns++)
                    mma_f16(acc[ms][ns], afr, bfr[ns]);
            }
        }
    }

    // ---------------- epilogue ----------------
    const float w = wst[1];
#pragma unroll
    for (int ms = 0; ms < 4; ms++) {
        const int r0 = rowA + wm * 64 + ms * 16 + (lane >> 2);
        const float ds0 = rds[r0] * w;
        const float ds1 = rds[r0 + 8] * w;
        if (GATED) {
#pragma unroll
            for (int ns = 0; ns < 4; ns++) {
                const int col = (rowB >> 1) + wn * 16 + ns * 4 + (lane & 3);
                float g0 = acc[ms][ns][0] * ds0;
                float v0 = acc[ms][ns][1] * ds0;
                float g1 = acc[ms][ns][2] * ds1;
                float v1 = acc[ms][ns][3] * ds1;
                C[(size_t)r0 * ldC + col]       = g0 * v0 * __fdiv_rn(1.0f, 1.0f + expf(-g0));
                C[(size_t)(r0 + 8) * ldC + col] = g1 * v1 * __fdiv_rn(1.0f, 1.0f + expf(-g1));
            }
        } else {
#pragma unroll
            for (int ns = 0; ns < 4; ns++) {
                const int col = rowB + wn * 32 + ns * 8 + ((lane & 3) << 1);
                float2 lo = make_float2(acc[ms][ns][0] * ds0, acc[ms][ns][1] * ds0);
                float2 hi = make_float2(acc[ms][ns][2] * ds1, acc[ms][ns][3] * ds1);
                *(float2*)(C + (size_t)r0 * ldC + col)       = lo;
                *(float2*)(C + (size_t)(r0 + 8) * ldC + col) = hi;
            }
        }
    }
}

// ---------------- launch --------------------------------------------------------
extern "C" void kernel_launch(void* const* d_in, const int* in_sizes, int n_in,
                              void* d_out, int out_size) {
    const float* x  = (const float*)d_in[0];
    const float* wg = (const float*)d_in[1];
    const float* wd = (const float*)d_in[2];
    float* out = (float*)d_out;

    void *p_wgq, *p_wdq, *p_xq, *p_hq, *p_xds, *p_hds, *p_h, *p_part, *p_sg, *p_sd;
    cudaGetSymbolAddress(&p_wgq, g_wgq);
    cudaGetSymbolAddress(&p_wdq, g_wdq);
    cudaGetSymbolAddress(&p_xq,  g_xq);
    cudaGetSymbolAddress(&p_hq,  g_hq);
    cudaGetSymbolAddress(&p_xds, g_xds);
    cudaGetSymbolAddress(&p_hds, g_hds);
    cudaGetSymbolAddress(&p_h,   g_h);
    cudaGetSymbolAddress(&p_part, g_part);
    cudaGetSymbolAddress(&p_sg,  g_sg);
    cudaGetSymbolAddress(&p_sd,  g_sd);

    cudaFuncSetAttribute(k_gemm_hmma<true>,  cudaFuncAttributeMaxDynamicSharedMemorySize, GSMEM);
    cudaFuncSetAttribute(k_gemm_hmma<false>, cudaFuncAttributeMaxDynamicSharedMemorySize, GSMEM);

    // weight scales (deterministic)
    k_absum_partial<<<2048, 256>>>(wg, (double*)p_part);
    k_absum_final<<<1, 256>>>((const double*)p_part, 2048, 1.0 / 33554432.0, (float*)p_sg);
    k_absum_partial<<<1024, 256>>>(wd, (double*)p_part);
    k_absum_final<<<1, 256>>>((const double*)p_part, 1024, 1.0 / 16777216.0, (float*)p_sd);

    // ternary quantize (w_gate row-interleaved), fp16 outputs
    k_quant_wg<<<8388608 / 256, 256>>>((const float4*)wg, (__half2*)p_wgq, (const float*)p_sg, 8388608);
    k_quant_w <<<4194304 / 256, 256>>>((const float4*)wd, (__half2*)p_wdq, (const float*)p_sd, 4194304);

    // RMSNorm + quant x (fp16 ints)
    k_rq_x<<<T_TOK, 256>>>(x, (__half*)p_xq, (float*)p_xds);

    // GEMM1 (gated): h[8192,8192] = silu(g)*v
    k_gemm_hmma<true><<<dim3(N1 / 128, T_TOK / 128), 256, GSMEM>>>(
        (const __half*)p_xq, (const __half*)p_wgq, (float*)p_h,
        (const float*)p_xds, (const float*)p_sg, HID, IMD);

    // RMSNorm + quant h (fp16 ints)
    k_rq_h<<<T_TOK, 256>>>((const float*)p_h, (__half*)p_hq, (float*)p_hds);

    // GEMM2: out[8192,2048]
    k_gemm_hmma<false><<<dim3(HID / 128, T_TOK / 128), 256, GSMEM>>>(
        (const __half*)p_hq, (const __half*)p_wdq, out,
        (const float*)p_hds, (const float*)p_sd, IMD, HID);
}

// round 5
// speedup vs baseline: 1.4682x; 1.0071x over previous
#include <cuda_runtime.h>
#include <cuda_fp16.h>
#include <cstdint>
#include <math.h>

// Problem dims (fixed)
#define T_TOK 8192          // B*S
#define HID   2048
#define IMD   8192
#define N1    16384         // 2*IMD

// ---------------- scratch ------------------------------------------------------
__device__ __half g_wgq[(size_t)N1 * HID];     // quantized w_gate (fp16 ints), (g,v) row-interleaved
__device__ __half g_wdq[(size_t)HID * IMD];    // quantized w_down (fp16 ints)
__device__ __half g_xq [(size_t)T_TOK * HID];  // quantized x (fp16 ints)
__device__ __half g_hq [(size_t)T_TOK * IMD];  // quantized hidden (fp16 ints)
__device__ float  g_xds[T_TOK];
__device__ float  g_hds[T_TOK];
__device__ float  g_h  [(size_t)T_TOK * IMD];  // silu(g)*v (fp32)
__device__ double g_part[4096];
__device__ float  g_sg[2];
__device__ float  g_sd[2];

// ---------------- PTX helpers ---------------------------------------------------
__device__ __forceinline__ uint32_t s2u(const void* p) {
    uint32_t a;
    asm("{ .reg .u64 t; cvta.to.shared.u64 t, %1; cvt.u32.u64 %0, t; }" : "=r"(a) : "l"(p));
    return a;
}

#define SWZ(o) ((o) ^ (((o) >> 3) & 0x70))

__device__ __forceinline__ void cp16(uint32_t s, const void* g) {
    asm volatile("cp.async.cg.shared.global [%0], [%1], 16;" :: "r"(s), "l"(g));
}

__device__ __forceinline__ void ldsm4(uint32_t* r, uint32_t addr) {
    asm volatile("ldmatrix.sync.aligned.m8n8.x4.shared.b16 {%0,%1,%2,%3}, [%4];"
        : "=r"(r[0]), "=r"(r[1]), "=r"(r[2]), "=r"(r[3]) : "r"(addr));
}
__device__ __forceinline__ void mma_f16(float* d, const uint32_t* a, const uint32_t* b) {
    asm volatile("mma.sync.aligned.m16n8k16.row.col.f32.f16.f16.f32 "
        "{%0,%1,%2,%3}, {%4,%5,%6,%7}, {%8,%9}, {%0,%1,%2,%3};"
        : "+f"(d[0]), "+f"(d[1]), "+f"(d[2]), "+f"(d[3])
        : "r"(a[0]), "r"(a[1]), "r"(a[2]), "r"(a[3]), "r"(b[0]), "r"(b[1]));
}

// ---------------- weight abs-mean (deterministic) ---------------------------------
__global__ void k_absum_partial(const float* __restrict__ w, double* __restrict__ part) {
    __shared__ double sm[256];
    const size_t base = (size_t)blockIdx.x * 16384;
    const float4* w4 = (const float4*)(w + base);
    double s = 0.0;
    for (int i = threadIdx.x; i < 4096; i += 256) {
        float4 v = w4[i];
        s += (double)fabsf(v.x) + (double)fabsf(v.y) + (double)fabsf(v.z) + (double)fabsf(v.w);
    }
    sm[threadIdx.x] = s; __syncthreads();
    for (int o = 128; o > 0; o >>= 1) {
        if (threadIdx.x < o) sm[threadIdx.x] += sm[threadIdx.x + o];
        __syncthreads();
    }
    if (threadIdx.x == 0) part[blockIdx.x] = sm[0];
}

__global__ void k_absum_final(const double* __restrict__ part, int G, double inv_n,
                              float* __restrict__ out2) {
    __shared__ double sm[256];
    double s = 0.0;
    for (int i = threadIdx.x; i < G; i += 256) s += part[i];
    sm[threadIdx.x] = s; __syncthreads();
    for (int o = 128; o > 0; o >>= 1) {
        if (threadIdx.x < o) sm[threadIdx.x] += sm[threadIdx.x + o];
        __syncthreads();
    }
    if (threadIdx.x == 0) {
        float mean = (float)(sm[0] * inv_n);
        float wm = fmaxf(mean, 1e-5f);
        float ws = __fdiv_rn(1.0f, wm);
        out2[0] = ws;
        out2[1] = __fdiv_rn(1.0f, ws);
    }
}

// ---------------- weight quant (ternary, emitted as fp16) --------------------------
__global__ void k_quant_w(const float4* __restrict__ w, __half2* __restrict__ q,
                          const float* __restrict__ st, int n4) {
    int i = blockIdx.x * 256 + threadIdx.x;
    if (i >= n4) return;
    const float ws = st[0];
    float4 v = w[i];
    float a = fminf(fmaxf(rintf(v.x * ws), -1.f), 1.f);
    float b = fminf(fmaxf(rintf(v.y * ws), -1.f), 1.f);
    float c = fminf(fmaxf(rintf(v.z * ws), -1.f), 1.f);
    float d = fminf(fmaxf(rintf(v.w * ws), -1.f), 1.f);
    q[2 * i]     = __floats2half2_rn(a, b);
    q[2 * i + 1] = __floats2half2_rn(c, d);
}

// gate/v row interleave: output row = (o<I) ? 2o : 2(o-I)+1
__global__ void k_quant_wg(const float4* __restrict__ w, __half2* __restrict__ q,
                           const float* __restrict__ st, int n4) {
    int i = blockIdx.x * 256 + threadIdx.x;
    if (i >= n4) return;
    const float ws = st[0];
    float4 v = w[i];
    float a = fminf(fmaxf(rintf(v.x * ws), -1.f), 1.f);
    float b = fminf(fmaxf(rintf(v.y * ws), -1.f), 1.f);
    float c = fminf(fmaxf(rintf(v.z * ws), -1.f), 1.f);
    float d = fminf(fmaxf(rintf(v.w * ws), -1.f), 1.f);
    const int rl4 = HID / 4;
    int orow = i / rl4, ccol = i - orow * rl4;
    int r = (orow < IMD) ? (orow << 1) : (((orow - IMD) << 1) + 1);
    __half2* qr = q + (size_t)r * (HID / 2) + ccol * 2;
    qr[0] = __floats2half2_rn(a, b);
    qr[1] = __floats2half2_rn(c, d);
}

__device__ __forceinline__ float rsqrt_acc(float v) {
    float r = rsqrtf(v);
    return r * (1.5f - 0.5f * v * r * r);
}

// ---------------- RMSNorm + quant (x, H=2048) -------------------------------------
__global__ void k_rq_x(const float* __restrict__ X, __half* __restrict__ Q,
                       float* __restrict__ dsd) {
    const int row = blockIdx.x, tid = threadIdx.x;
    const float* xr = X + (size_t)row * HID;
    __shared__ float s1[256], s2[256];
    float ss = 0.f, am = 0.f, xv[8];
#pragma unroll
    for (int k = 0; k < 8; k++) {
        float v = xr[tid + k * 256];
        xv[k] = v; ss += v * v; am = fmaxf(am, fabsf(v));
    }
    s1[tid] = ss; s2[tid] = am; __syncthreads();
    for (int o = 128; o > 0; o >>= 1) {
        if (tid < o) { s1[tid] += s1[tid + o]; s2[tid] = fmaxf(s2[tid], s2[tid + o]); }
        __syncthreads();
    }
    const float r  = rsqrt_acc(s1[0] * (1.0f / HID) + 1e-8f);
    const float sc = __fdiv_rn(127.0f, fmaxf(s2[0] * r, 1e-5f));
    __half* qr = Q + (size_t)row * HID;
#pragma unroll
    for (int k = 0; k < 8; k++)
        qr[tid + k * 256] = __float2half_rn(fminf(fmaxf(rintf(xv[k] * r * sc), -128.f), 127.f));
    if (tid == 0) dsd[row] = __fdiv_rn(1.0f, sc);
}

// ---------------- RMSNorm + quant (h, I=8192) --------------------------------------
__global__ void k_rq_h(const float* __restrict__ X, __half* __restrict__ Q,
                       float* __restrict__ dsd) {
    const int row = blockIdx.x, tid = threadIdx.x;
    const float* xr = X + (size_t)row * IMD;
    __shared__ float s1[256], s2[256];
    float ss = 0.f, am = 0.f, xv[32];
#pragma unroll
    for (int k = 0; k < 32; k++) {
        float v = xr[tid + k * 256];
        xv[k] = v; ss += v * v; am = fmaxf(am, fabsf(v));
    }
    s1[tid] = ss; s2[tid] = am; __syncthreads();
    for (int o = 128; o > 0; o >>= 1) {
        if (tid < o) { s1[tid] += s1[tid + o]; s2[tid] = fmaxf(s2[tid], s2[tid + o]); }
        __syncthreads();
    }
    const float r  = rsqrt_acc(s1[0] * (1.0f / IMD) + 1e-8f);
    const float sc = __fdiv_rn(127.0f, fmaxf(s2[0] * r, 1e-5f));
    __half* qr = Q + (size_t)row * IMD;
#pragma unroll
    for (int k = 0; k < 32; k++)
        qr[tid + k * 256] = __float2half_rn(fminf(fmaxf(rintf(xv[k] * r * sc), -128.f), 127.f));
    if (tid == 0) dsd[row] = __fdiv_rn(1.0f, sc);
}

// ---------------- fp16 HMMA GEMM (exact integer math) -------------------------------
// CTA tile 128x128, K-tile 64 (128B rows, SW128), 3-stage cp.async, 8 warps (2x4),
// warp tile 64x32. B fragments fetched in ks-PAIRS via ldmatrix.x4 (half the LDSM).
// GATED: B rows interleaved (gate,v) -> epilogue silu(g)*v, output width N/2.
static const int GSMEM = 3 * 32768 + 128;

template<bool GATED>
__global__ void __launch_bounds__(256, 2)
k_gemm_hmma(const __half* __restrict__ A, const __half* __restrict__ B,
            float* __restrict__ C, const float* __restrict__ rds,
            const float* __restrict__ wst, int K, int ldC) {
    extern __shared__ char dsm[];
    const uint32_t base = (s2u(dsm) + 127u) & ~127u;
    const int tid  = threadIdx.x;
    const int lane = tid & 31;
    const int warp = tid >> 5;
    const int wm = warp >> 2;          // 0..1
    const int wn = warp & 3;           // 0..3
    const int rowA = blockIdx.y << 7;
    const int rowB = blockIdx.x << 7;
    const int KT = K >> 6;

    // loader: threads 0..127 -> A rows, 128..255 -> B rows; 8 x 16B per thread
    const int lr = tid & 127;
    const int ab = tid >> 7;
    const char* gsrc = (const char*)((ab ? B : A) + (size_t)((ab ? rowB : rowA) + lr) * K);
    uint32_t dst[8];
#pragma unroll
    for (int c = 0; c < 8; c++)
        dst[c] = base + ab * 16384 + SWZ((uint32_t)(lr * 128 + c * 16));

#define LD_STAGE(j) do { \
    const uint32_t off = ((j) % 3) * 32768; \
    const char* gp = gsrc + (size_t)(j) * 128; \
    _Pragma("unroll") for (int c = 0; c < 8; c++) cp16(dst[c] + off, gp + c * 16); \
} while (0)

    float acc[4][4][4];
#pragma unroll
    for (int i = 0; i < 4; i++)
#pragma unroll
        for (int j = 0; j < 4; j++)
#pragma unroll
            for (int k = 0; k < 4; k++) acc[i][j][k] = 0.f;

    LD_STAGE(0); asm volatile("cp.async.commit_group;");
    LD_STAGE(1); asm volatile("cp.async.commit_group;");

    // ldmatrix per-lane address components
    const int arow = lane & 15;          // A: + wm*64 + ms*16
    const int achk = lane >> 4;          // A: + ks*2
    const int brow = lane & 7;           // B: + wn*32 + ns*8
    const int bchk = lane >> 3;          // B: + kp*4  (x4: 4 chunks = ks-pair)

    for (int j = 0; j < KT; j++) {
        asm volatile("cp.async.wait_group 1;");
        __syncthreads();
        if (j + 2 < KT) LD_STAGE(j + 2);
        asm volatile("cp.async.commit_group;");

        const uint32_t aB = base + (j % 3) * 32768;
        const uint32_t bB = aB + 16384;
#pragma unroll
        for (int kp = 0; kp < 2; kp++) {
            // one ldsm4 per ns covers BOTH k-steps of the pair:
            // regs [0,1] = frag for ks=2kp, regs [2,3] = frag for ks=2kp+1
            uint32_t bfr[4][4];
#pragma unroll
            for (int ns = 0; ns < 4; ns++)
                ldsm4(bfr[ns], bB + SWZ((uint32_t)((wn * 32 + ns * 8 + brow) * 128 +
                                                   (kp * 4 + bchk) * 16)));
#pragma unroll
            for (int kk = 0; kk < 2; kk++) {
                const int ks = kp * 2 + kk;
#pragma unroll
                for (int ms = 0; ms < 4; ms++) {
                    uint32_t afr[4];
                    ldsm4(afr, aB + SWZ((uint32_t)((wm * 64 + ms * 16 + arow) * 128 +
                                                   (ks * 2 + achk) * 16)));
#pragma unroll
                    for (int ns = 0; ns < 4; ns++)
                        mma_f16(acc[ms][ns], afr, &bfr[ns][kk * 2]);
                }
            }
        }
    }

    // ---------------- epilogue ----------------
    const float w = wst[1];
#pragma unroll
    for (int ms = 0; ms < 4; ms++) {
        const int r0 = rowA + wm * 64 + ms * 16 + (lane >> 2);
        const float ds0 = rds[r0] * w;
        const float ds1 = rds[r0 + 8] * w;
        if (GATED) {
#pragma unroll
            for (int ns = 0; ns < 4; ns++) {
                const int col = (rowB >> 1) + wn * 16 + ns * 4 + (lane & 3);
                float g0 = acc[ms][ns][0] * ds0;
                float v0 = acc[ms][ns][1] * ds0;
                float g1 = acc[ms][ns][2] * ds1;
                float v1 = acc[ms][ns][3] * ds1;
                C[(size_t)r0 * ldC + col]       = g0 * v0 * __fdiv_rn(1.0f, 1.0f + expf(-g0));
                C[(size_t)(r0 + 8) * ldC + col] = g1 * v1 * __fdiv_rn(1.0f, 1.0f + expf(-g1));
            }
        } else {
#pragma unroll
            for (int ns = 0; ns < 4; ns++) {
                const int col = rowB + wn * 32 + ns * 8 + ((lane & 3) << 1);
                float2 lo = make_float2(acc[ms][ns][0] * ds0, acc[ms][ns][1] * ds0);
                float2 hi = make_float2(acc[ms][ns][2] * ds1, acc[ms][ns][3] * ds1);
                *(float2*)(C + (size_t)r0 * ldC + col)       = lo;
                *(float2*)(C + (size_t)(r0 + 8) * ldC + col) = hi;
            }
        }
    }
}

// ---------------- launch --------------------------------------------------------
// Launch order is arranged so GEMM1 sits at launch index 5 (ncu -s 5 -c 1 target).
extern "C" void kernel_launch(void* const* d_in, const int* in_sizes, int n_in,
                              void* d_out, int out_size) {
    const float* x  = (const float*)d_in[0];
    const float* wg = (const float*)d_in[1];
    const float* wd = (const float*)d_in[2];
    float* out = (float*)d_out;

    void *p_wgq, *p_wdq, *p_xq, *p_hq, *p_xds, *p_hds, *p_h, *p_part, *p_part2, *p_sg, *p_sd;
    cudaGetSymbolAddress(&p_wgq, g_wgq);
    cudaGetSymbolAddress(&p_wdq, g_wdq);
    cudaGetSymbolAddress(&p_xq,  g_xq);
    cudaGetSymbolAddress(&p_hq,  g_hq);
    cudaGetSymbolAddress(&p_xds, g_xds);
    cudaGetSymbolAddress(&p_hds, g_hds);
    cudaGetSymbolAddress(&p_h,   g_h);
    cudaGetSymbolAddress(&p_part, g_part);
    p_part2 = (void*)((double*)p_part + 2048);
    cudaGetSymbolAddress(&p_sg,  g_sg);
    cudaGetSymbolAddress(&p_sd,  g_sd);

    cudaFuncSetAttribute(k_gemm_hmma<true>,  cudaFuncAttributeMaxDynamicSharedMemorySize, GSMEM);
    cudaFuncSetAttribute(k_gemm_hmma<false>, cudaFuncAttributeMaxDynamicSharedMemorySize, GSMEM);

    // [0] w_gate abs-sum partials
    k_absum_partial<<<2048, 256>>>(wg, (double*)p_part);
    // [1] w_gate scale
    k_absum_final<<<1, 256>>>((const double*)p_part, 2048, 1.0 / 33554432.0, (float*)p_sg);
    // [2] quantize w_gate (row-interleaved, fp16)
    k_quant_wg<<<8388608 / 256, 256>>>((const float4*)wg, (__half2*)p_wgq, (const float*)p_sg, 8388608);
    // [3] RMSNorm + quant x
    k_rq_x<<<T_TOK, 256>>>(x, (__half*)p_xq, (float*)p_xds);
    // [4] w_down abs-sum partials (independent; placed here so GEMM1 lands at index 5)
    k_absum_partial<<<1024, 256>>>(wd, (double*)p_part2);
    // [5] GEMM1 (gated): h[8192,8192] = silu(g)*v
    k_gemm_hmma<true><<<dim3(N1 / 128, T_TOK / 128), 256, GSMEM>>>(
        (const __half*)p_xq, (const __half*)p_wgq, (float*)p_h,
        (const float*)p_xds, (const float*)p_sg, HID, IMD);
    // [6] w_down scale
    k_absum_final<<<1, 256>>>((const double*)p_part2, 1024, 1.0 / 16777216.0, (float*)p_sd);
    // [7] quantize w_down
    k_quant_w<<<4194304 / 256, 256>>>((const float4*)wd, (__half2*)p_wdq, (const float*)p_sd, 4194304);
    // [8] RMSNorm + quant h
    k_rq_h<<<T_TOK, 256>>>((const float*)p_h, (__half*)p_hq, (float*)p_hds);
    // [9] GEMM2: out[8192,2048]
    k_gemm_hmma<false><<<dim3(HID / 128, T_TOK / 128), 256, GSMEM>>>(
        (const __half*)p_hq, (const __half*)p_wdq, out,
        (const float*)p_hds, (const float*)p_sd, IMD, HID);
}

// round 6
// speedup vs baseline: 1.8997x; 1.2939x over previous
#include <cuda_runtime.h>
#include <cuda_fp16.h>
#include <cstdint>
#include <math.h>

// Problem dims (fixed)
#define T_TOK 8192          // B*S
#define HID   2048
#define IMD   8192
#define N1    16384         // 2*IMD

// ---------------- scratch ------------------------------------------------------
__device__ __half g_wgq[(size_t)N1 * HID];     // quantized w_gate (fp16 ints), (g,v) row-interleaved
__device__ __half g_wdq[(size_t)HID * IMD];    // quantized w_down (fp16 ints)
__device__ __half g_xq [(size_t)T_TOK * HID];  // quantized x (fp16 ints)
__device__ __half g_hq [(size_t)T_TOK * IMD];  // quantized hidden (fp16 ints)
__device__ float  g_xds[T_TOK];
__device__ float  g_hds[T_TOK];
__device__ float  g_h  [(size_t)T_TOK * IMD];  // silu(g)*v (fp32)
__device__ unsigned long long g_acc[2];        // fixed-point |w| sums (wg, wd)

// ---------------- PTX helpers ---------------------------------------------------
__device__ __forceinline__ uint32_t s2u(const void* p) {
    uint32_t a;
    asm("{ .reg .u64 t; cvta.to.shared.u64 t, %1; cvt.u32.u64 %0, t; }" : "=r"(a) : "l"(p));
    return a;
}

#define SWZ(o) ((o) ^ (((o) >> 3) & 0x70))

__device__ __forceinline__ void cp16(uint32_t s, const void* g) {
    asm volatile("cp.async.cg.shared.global [%0], [%1], 16;" :: "r"(s), "l"(g));
}

__device__ __forceinline__ void ldsm4(uint32_t* r, uint32_t addr) {
    asm volatile("ldmatrix.sync.aligned.m8n8.x4.shared.b16 {%0,%1,%2,%3}, [%4];"
        : "=r"(r[0]), "=r"(r[1]), "=r"(r[2]), "=r"(r[3]) : "r"(addr));
}
__device__ __forceinline__ void mma_f16(float* d, const uint32_t* a, const uint32_t* b) {
    asm volatile("mma.sync.aligned.m16n8k16.row.col.f32.f16.f16.f32 "
        "{%0,%1,%2,%3}, {%4,%5,%6,%7}, {%8,%9}, {%0,%1,%2,%3};"
        : "+f"(d[0]), "+f"(d[1]), "+f"(d[2]), "+f"(d[3])
        : "r"(a[0]), "r"(a[1]), "r"(a[2]), "r"(a[3]), "r"(b[0]), "r"(b[1]));
}

// weight-scale clip(mean|w|, 1e-5) from the fixed-point accumulator
__device__ __forceinline__ float wm_from(const unsigned long long* acc, double inv_n) {
    double mean = (double)(long long)(*acc) * (1.0 / 67108864.0) * inv_n;
    return fmaxf((float)mean, 1e-5f);
}

// ---------------- weight abs-sum: ONE kernel, order-independent fixed point --------
__global__ void k_absum_u64(const float* __restrict__ w, unsigned long long* __restrict__ acc) {
    __shared__ unsigned long long sm[256];
    const size_t base = (size_t)blockIdx.x * 16384;
    const float4* w4 = (const float4*)(w + base);
    unsigned long long s = 0;
    for (int i = threadIdx.x; i < 4096; i += 256) {
        float4 v = w4[i];
        s += (unsigned long long)llrintf(fabsf(v.x) * 67108864.f);
        s += (unsigned long long)llrintf(fabsf(v.y) * 67108864.f);
        s += (unsigned long long)llrintf(fabsf(v.z) * 67108864.f);
        s += (unsigned long long)llrintf(fabsf(v.w) * 67108864.f);
    }
    sm[threadIdx.x] = s; __syncthreads();
    for (int o = 128; o > 0; o >>= 1) {
        if (threadIdx.x < o) sm[threadIdx.x] += sm[threadIdx.x + o];
        __syncthreads();
    }
    if (threadIdx.x == 0) atomicAdd(acc, sm[0]);
}

// ---------------- weight quant (ternary, fp16 out) ---------------------------------
__global__ void k_quant_w(const float4* __restrict__ w, __half2* __restrict__ q,
                          const unsigned long long* __restrict__ acc, double inv_n, int n4) {
    int i = blockIdx.x * 256 + threadIdx.x;
    if (i >= n4) return;
    const float ws = __fdiv_rn(1.0f, wm_from(acc, inv_n));
    float4 v = w[i];
    float a = fminf(fmaxf(rintf(v.x * ws), -1.f), 1.f);
    float b = fminf(fmaxf(rintf(v.y * ws), -1.f), 1.f);
    float c = fminf(fmaxf(rintf(v.z * ws), -1.f), 1.f);
    float d = fminf(fmaxf(rintf(v.w * ws), -1.f), 1.f);
    q[2 * i]     = __floats2half2_rn(a, b);
    q[2 * i + 1] = __floats2half2_rn(c, d);
}

// gate/v row interleave: output row = (o<I) ? 2o : 2(o-I)+1
__global__ void k_quant_wg(const float4* __restrict__ w, __half2* __restrict__ q,
                           const unsigned long long* __restrict__ acc, double inv_n, int n4) {
    int i = blockIdx.x * 256 + threadIdx.x;
    if (i >= n4) return;
    const float ws = __fdiv_rn(1.0f, wm_from(acc, inv_n));
    float4 v = w[i];
    float a = fminf(fmaxf(rintf(v.x * ws), -1.f), 1.f);
    float b = fminf(fmaxf(rintf(v.y * ws), -1.f), 1.f);
    float c = fminf(fmaxf(rintf(v.z * ws), -1.f), 1.f);
    float d = fminf(fmaxf(rintf(v.w * ws), -1.f), 1.f);
    const int rl4 = HID / 4;
    int orow = i / rl4, ccol = i - orow * rl4;
    int r = (orow < IMD) ? (orow << 1) : (((orow - IMD) << 1) + 1);
    __half2* qr = q + (size_t)r * (HID / 2) + ccol * 2;
    qr[0] = __floats2half2_rn(a, b);
    qr[1] = __floats2half2_rn(c, d);
}

__device__ __forceinline__ float rsqrt_acc(float v) {
    float r = rsqrtf(v);
    return r * (1.5f - 0.5f * v * r * r);
}

// ---------------- RMSNorm + quant (x, H=2048); also zeroes the accumulators --------
__global__ void k_rq_x(const float* __restrict__ X, __half* __restrict__ Q,
                       float* __restrict__ dsd, unsigned long long* __restrict__ acc) {
    const int row = blockIdx.x, tid = threadIdx.x;
    if (row == 0 && tid < 2) acc[tid] = 0ull;   // reset for this call (graph replay safe)
    const float* xr = X + (size_t)row * HID;
    __shared__ float s1[256], s2[256];
    float ss = 0.f, am = 0.f, xv[8];
#pragma unroll
    for (int k = 0; k < 8; k++) {
        float v = xr[tid + k * 256];
        xv[k] = v; ss += v * v; am = fmaxf(am, fabsf(v));
    }
    s1[tid] = ss; s2[tid] = am; __syncthreads();
    for (int o = 128; o > 0; o >>= 1) {
        if (tid < o) { s1[tid] += s1[tid + o]; s2[tid] = fmaxf(s2[tid], s2[tid + o]); }
        __syncthreads();
    }
    const float r  = rsqrt_acc(s1[0] * (1.0f / HID) + 1e-8f);
    const float sc = __fdiv_rn(127.0f, fmaxf(s2[0] * r, 1e-5f));
    __half* qr = Q + (size_t)row * HID;
#pragma unroll
    for (int k = 0; k < 8; k++)
        qr[tid + k * 256] = __float2half_rn(fminf(fmaxf(rintf(xv[k] * r * sc), -128.f), 127.f));
    if (tid == 0) dsd[row] = __fdiv_rn(1.0f, sc);
}

// ---------------- RMSNorm + quant (h, I=8192) --------------------------------------
__global__ void k_rq_h(const float* __restrict__ X, __half* __restrict__ Q,
                       float* __restrict__ dsd) {
    const int row = blockIdx.x, tid = threadIdx.x;
    const float* xr = X + (size_t)row * IMD;
    __shared__ float s1[256], s2[256];
    float ss = 0.f, am = 0.f, xv[32];
#pragma unroll
    for (int k = 0; k < 32; k++) {
        float v = xr[tid + k * 256];
        xv[k] = v; ss += v * v; am = fmaxf(am, fabsf(v));
    }
    s1[tid] = ss; s2[tid] = am; __syncthreads();
    for (int o = 128; o > 0; o >>= 1) {
        if (tid < o) { s1[tid] += s1[tid + o]; s2[tid] = fmaxf(s2[tid], s2[tid + o]); }
        __syncthreads();
    }
    const float r  = rsqrt_acc(s1[0] * (1.0f / IMD) + 1e-8f);
    const float sc = __fdiv_rn(127.0f, fmaxf(s2[0] * r, 1e-5f));
    __half* qr = Q + (size_t)row * IMD;
#pragma unroll
    for (int k = 0; k < 32; k++)
        qr[tid + k * 256] = __float2half_rn(fminf(fmaxf(rintf(xv[k] * r * sc), -128.f), 127.f));
    if (tid == 0) dsd[row] = __fdiv_rn(1.0f, sc);
}

// ---------------- fp16 HMMA GEMM (exact integer math) -------------------------------
// CTA tile 128x128, K-tile 64, 3-stage cp.async, 512 threads / 16 warps (4x4),
// warp tile 32x32 -> acc only 32 regs/thread: no spill under 128-reg budget.
// GATED: B rows interleaved (gate,v) -> epilogue silu(g)*v, output width N/2.
static const int GSMEM = 3 * 32768 + 256;

template<bool GATED>
__global__ void __launch_bounds__(512, 1)
k_gemm_hmma(const __half* __restrict__ A, const __half* __restrict__ B,
            float* __restrict__ C, const float* __restrict__ rds,
            const unsigned long long* __restrict__ acc, double inv_n, int K, int ldC) {
    extern __shared__ char dsm[];
    const uint32_t base = (s2u(dsm) + 127u) & ~127u;
    const int tid  = threadIdx.x;
    const int lane = tid & 31;
    const int warp = tid >> 5;
    const int wm4 = warp >> 2;         // 0..3 (m groups of 32)
    const int wn4 = warp & 3;          // 0..3 (n groups of 32)
    const int rowA = blockIdx.y << 7;
    const int rowB = blockIdx.x << 7;
    const int KT = K >> 6;

    // loader: threads 0..255 -> A (128 rows x 128B), 256..511 -> B; 4 x 16B each
    const int lr  = tid & 255;
    const int ab  = tid >> 8;
    const int row = lr >> 1;
    const int cb  = (lr & 1) << 2;       // chunk base 0 or 4
    const char* gsrc = (const char*)((ab ? B : A) + (size_t)((ab ? rowB : rowA) + row) * K)
                       + cb * 16;
    uint32_t dst[4];
#pragma unroll
    for (int c = 0; c < 4; c++)
        dst[c] = base + ab * 16384 + SWZ((uint32_t)(row * 128 + (cb + c) * 16));

#define LD_STAGE(j) do { \
    const uint32_t off = ((j) % 3) * 32768; \
    const char* gp = gsrc + (size_t)(j) * 128; \
    _Pragma("unroll") for (int c = 0; c < 4; c++) cp16(dst[c] + off, gp + c * 16); \
} while (0)

    float fa[2][4][4];
#pragma unroll
    for (int i = 0; i < 2; i++)
#pragma unroll
        for (int j = 0; j < 4; j++)
#pragma unroll
            for (int k = 0; k < 4; k++) fa[i][j][k] = 0.f;

    LD_STAGE(0); asm volatile("cp.async.commit_group;");
    LD_STAGE(1); asm volatile("cp.async.commit_group;");

    // ldmatrix per-lane address components
    const int arow = lane & 15;          // A: + wm4*32 + ms*16
    const int achk = lane >> 4;          // A: + ks*2
    const int brow = lane & 7;           // B: + wn4*32 + ns*8
    const int bchk = lane >> 3;          // B: + kp*4

    for (int j = 0; j < KT; j++) {
        asm volatile("cp.async.wait_group 1;");
        __syncthreads();
        if (j + 2 < KT) LD_STAGE(j + 2);
        asm volatile("cp.async.commit_group;");

        const uint32_t aB = base + (j % 3) * 32768;
        const uint32_t bB = aB + 16384;
#pragma unroll
        for (int kp = 0; kp < 2; kp++) {
            // one ldsm4 per ns covers both k-steps of the pair
            uint32_t bfr[4][4];
#pragma unroll
            for (int ns = 0; ns < 4; ns++)
                ldsm4(bfr[ns], bB + SWZ((uint32_t)((wn4 * 32 + ns * 8 + brow) * 128 +
                                                   (kp * 4 + bchk) * 16)));
#pragma unroll
            for (int kk = 0; kk < 2; kk++) {
                const int ks = kp * 2 + kk;
#pragma unroll
                for (int ms = 0; ms < 2; ms++) {
                    uint32_t afr[4];
                    ldsm4(afr, aB + SWZ((uint32_t)((wm4 * 32 + ms * 16 + arow) * 128 +
                                                   (ks * 2 + achk) * 16)));
#pragma unroll
                    for (int ns = 0; ns < 4; ns++)
                        mma_f16(fa[ms][ns], afr, &bfr[ns][kk * 2]);
                }
            }
        }
    }

    // ---------------- epilogue ----------------
    const float wmv = wm_from(acc, inv_n);
#pragma unroll
    for (int ms = 0; ms < 2; ms++) {
        const int r0 = rowA + wm4 * 32 + ms * 16 + (lane >> 2);
        const float ds0 = rds[r0] * wmv;
        const float ds1 = rds[r0 + 8] * wmv;
        if (GATED) {
#pragma unroll
            for (int ns = 0; ns < 4; ns++) {
                const int col = (rowB >> 1) + wn4 * 16 + ns * 4 + (lane & 3);
                float g0 = fa[ms][ns][0] * ds0;
                float v0 = fa[ms][ns][1] * ds0;
                float g1 = fa[ms][ns][2] * ds1;
                float v1 = fa[ms][ns][3] * ds1;
                C[(size_t)r0 * ldC + col]       = g0 * v0 * __fdiv_rn(1.0f, 1.0f + expf(-g0));
                C[(size_t)(r0 + 8) * ldC + col] = g1 * v1 * __fdiv_rn(1.0f, 1.0f + expf(-g1));
            }
        } else {
#pragma unroll
            for (int ns = 0; ns < 4; ns++) {
                const int col = rowB + wn4 * 32 + ns * 8 + ((lane & 3) << 1);
                float2 lo = make_float2(fa[ms][ns][0] * ds0, fa[ms][ns][1] * ds0);
                float2 hi = make_float2(fa[ms][ns][2] * ds1, fa[ms][ns][3] * ds1);
                *(float2*)(C + (size_t)r0 * ldC + col)       = lo;
                *(float2*)(C + (size_t)(r0 + 8) * ldC + col) = hi;
            }
        }
    }
}

// ---------------- launch --------------------------------------------------------
// GEMM1 sits at my launch index 3 (harness prepends 2 launches; ncu -s 5 catches idx 3).
extern "C" void kernel_launch(void* const* d_in, const int* in_sizes, int n_in,
                              void* d_out, int out_size) {
    const float* x  = (const float*)d_in[0];
    const float* wg = (const float*)d_in[1];
    const float* wd = (const float*)d_in[2];
    float* out = (float*)d_out;

    void *p_wgq, *p_wdq, *p_xq, *p_hq, *p_xds, *p_hds, *p_h, *p_acc;
    cudaGetSymbolAddress(&p_wgq, g_wgq);
    cudaGetSymbolAddress(&p_wdq, g_wdq);
    cudaGetSymbolAddress(&p_xq,  g_xq);
    cudaGetSymbolAddress(&p_hq,  g_hq);
    cudaGetSymbolAddress(&p_xds, g_xds);
    cudaGetSymbolAddress(&p_hds, g_hds);
    cudaGetSymbolAddress(&p_h,   g_h);
    cudaGetSymbolAddress(&p_acc, g_acc);
    unsigned long long* acc0 = (unsigned long long*)p_acc;
    unsigned long long* acc1 = acc0 + 1;
    const double INV_WG = 1.0 / 33554432.0;
    const double INV_WD = 1.0 / 16777216.0;

    cudaFuncSetAttribute(k_gemm_hmma<true>,  cudaFuncAttributeMaxDynamicSharedMemorySize, GSMEM);
    cudaFuncSetAttribute(k_gemm_hmma<false>, cudaFuncAttributeMaxDynamicSharedMemorySize, GSMEM);

    // [0] RMSNorm + quant x (also zeroes accumulators)
    k_rq_x<<<T_TOK, 256>>>(x, (__half*)p_xq, (float*)p_xds, acc0);
    // [1] w_gate |w| fixed-point sum (single kernel, order-independent)
    k_absum_u64<<<2048, 256>>>(wg, acc0);
    // [2] quantize w_gate (row-interleaved, fp16)
    k_quant_wg<<<8388608 / 256, 256>>>((const float4*)wg, (__half2*)p_wgq, acc0, INV_WG, 8388608);
    // [3] GEMM1 (gated): h[8192,8192] = silu(g)*v        <-- ncu capture target
    k_gemm_hmma<true><<<dim3(N1 / 128, T_TOK / 128), 512, GSMEM>>>(
        (const __half*)p_xq, (const __half*)p_wgq, (float*)p_h,
        (const float*)p_xds, acc0, INV_WG, HID, IMD);
    // [4] w_down |w| fixed-point sum
    k_absum_u64<<<1024, 256>>>(wd, acc1);
    // [5] quantize w_down
    k_quant_w<<<4194304 / 256, 256>>>((const float4*)wd, (__half2*)p_wdq, acc1, INV_WD, 4194304);
    // [6] RMSNorm + quant h
    k_rq_h<<<T_TOK, 256>>>((const float*)p_h, (__half*)p_hq, (float*)p_hds);
    // [7] GEMM2: out[8192,2048]
    k_gemm_hmma<false><<<dim3(HID / 128, T_TOK / 128), 512, GSMEM>>>(
        (const __half*)p_hq, (const __half*)p_wdq, out,
        (const float*)p_hds, acc1, INV_WD, IMD, HID);
}

// round 8
// speedup vs baseline: 1.9447x; 1.0237x over previous
#include <cuda_runtime.h>
#include <cuda_fp16.h>
#include <cstdint>
#include <math.h>

// Problem dims (fixed)
#define T_TOK 8192          // B*S
#define HID   2048
#define IMD   8192
#define N1    16384         // 2*IMD

// ---------------- scratch ------------------------------------------------------
__device__ __half g_wgq[(size_t)N1 * HID];     // quantized w_gate (fp16 ints), (g,v) row-interleaved
__device__ __half g_wdq[(size_t)HID * IMD];    // quantized w_down (fp16 ints)
__device__ __half g_xq [(size_t)T_TOK * HID];  // quantized x (fp16 ints)
__device__ __half g_hq [(size_t)T_TOK * IMD];  // quantized hidden (fp16 ints)
__device__ float  g_xds[T_TOK];
__device__ float  g_hds[T_TOK];
__device__ float  g_h  [(size_t)T_TOK * IMD];  // silu(g)*v (fp32)
__device__ unsigned long long g_acc[2];        // fixed-point |w| sums (wg, wd)

// ---------------- PTX helpers ---------------------------------------------------
__device__ __forceinline__ uint32_t s2u(const void* p) {
    uint32_t a;
    asm("{ .reg .u64 t; cvta.to.shared.u64 t, %1; cvt.u32.u64 %0, t; }" : "=r"(a) : "l"(p));
    return a;
}

#define SWZ(o) ((o) ^ (((o) >> 3) & 0x70))

__device__ __forceinline__ void cp16(uint32_t s, const void* g) {
    asm volatile("cp.async.cg.shared.global [%0], [%1], 16;" :: "r"(s), "l"(g));
}

__device__ __forceinline__ void ldsm4(uint32_t* r, uint32_t addr) {
    asm volatile("ldmatrix.sync.aligned.m8n8.x4.shared.b16 {%0,%1,%2,%3}, [%4];"
        : "=r"(r[0]), "=r"(r[1]), "=r"(r[2]), "=r"(r[3]) : "r"(addr));
}
__device__ __forceinline__ void mma_f16(float* d, const uint32_t* a, const uint32_t* b) {
    asm volatile("mma.sync.aligned.m16n8k16.row.col.f32.f16.f16.f32 "
        "{%0,%1,%2,%3}, {%4,%5,%6,%7}, {%8,%9}, {%0,%1,%2,%3};"
        : "+f"(d[0]), "+f"(d[1]), "+f"(d[2]), "+f"(d[3])
        : "r"(a[0]), "r"(a[1]), "r"(a[2]), "r"(a[3]), "r"(b[0]), "r"(b[1]));
}

// weight-scale clip(mean|w|, 1e-5) from the fixed-point accumulator
__device__ __forceinline__ float wm_from(const unsigned long long* acc, double inv_n) {
    double mean = (double)(long long)(*acc) * (1.0 / 67108864.0) * inv_n;
    return fmaxf((float)mean, 1e-5f);
}

// ---------------- weight abs-sum: order-independent fixed point --------------------
__global__ void k_absum_u64(const float* __restrict__ w, unsigned long long* __restrict__ acc) {
    __shared__ unsigned long long sm[256];
    const size_t base = (size_t)blockIdx.x * 16384;
    const float4* w4 = (const float4*)(w + base);
    unsigned long long s = 0;
    for (int i = threadIdx.x; i < 4096; i += 256) {
        float4 v = w4[i];
        s += (unsigned long long)llrintf(fabsf(v.x) * 67108864.f);
        s += (unsigned long long)llrintf(fabsf(v.y) * 67108864.f);
        s += (unsigned long long)llrintf(fabsf(v.z) * 67108864.f);
        s += (unsigned long long)llrintf(fabsf(v.w) * 67108864.f);
    }
    sm[threadIdx.x] = s; __syncthreads();
    for (int o = 128; o > 0; o >>= 1) {
        if (threadIdx.x < o) sm[threadIdx.x] += sm[threadIdx.x + o];
        __syncthreads();
    }
    if (threadIdx.x == 0) atomicAdd(acc, sm[0]);
}

// ---------------- weight quant (ternary, fp16 out) ---------------------------------
__global__ void k_quant_w(const float4* __restrict__ w, __half2* __restrict__ q,
                          const unsigned long long* __restrict__ acc, double inv_n, int n4) {
    int i = blockIdx.x * 256 + threadIdx.x;
    if (i >= n4) return;
    const float ws = __fdiv_rn(1.0f, wm_from(acc, inv_n));
    float4 v = w[i];
    float a = fminf(fmaxf(rintf(v.x * ws), -1.f), 1.f);
    float b = fminf(fmaxf(rintf(v.y * ws), -1.f), 1.f);
    float c = fminf(fmaxf(rintf(v.z * ws), -1.f), 1.f);
    float d = fminf(fmaxf(rintf(v.w * ws), -1.f), 1.f);
    q[2 * i]     = __floats2half2_rn(a, b);
    q[2 * i + 1] = __floats2half2_rn(c, d);
}

// gate/v row interleave: output row = (o<I) ? 2o : 2(o-I)+1
__global__ void k_quant_wg(const float4* __restrict__ w, __half2* __restrict__ q,
                           const unsigned long long* __restrict__ acc, double inv_n, int n4) {
    int i = blockIdx.x * 256 + threadIdx.x;
    if (i >= n4) return;
    const float ws = __fdiv_rn(1.0f, wm_from(acc, inv_n));
    float4 v = w[i];
    float a = fminf(fmaxf(rintf(v.x * ws), -1.f), 1.f);
    float b = fminf(fmaxf(rintf(v.y * ws), -1.f), 1.f);
    float c = fminf(fmaxf(rintf(v.z * ws), -1.f), 1.f);
    float d = fminf(fmaxf(rintf(v.w * ws), -1.f), 1.f);
    const int rl4 = HID / 4;
    int orow = i / rl4, ccol = i - orow * rl4;
    int r = (orow < IMD) ? (orow << 1) : (((orow - IMD) << 1) + 1);
    __half2* qr = q + (size_t)r * (HID / 2) + ccol * 2;
    qr[0] = __floats2half2_rn(a, b);
    qr[1] = __floats2half2_rn(c, d);
}

__device__ __forceinline__ float rsqrt_acc(float v) {
    float r = rsqrtf(v);
    return r * (1.5f - 0.5f * v * r * r);
}

// ---------------- RMSNorm + quant (x, H=2048); also zeroes the accumulators --------
__global__ void k_rq_x(const float* __restrict__ X, __half* __restrict__ Q,
                       float* __restrict__ dsd, unsigned long long* __restrict__ acc) {
    const int row = blockIdx.x, tid = threadIdx.x;
    if (row == 0 && tid < 2) acc[tid] = 0ull;
    const float* xr = X + (size_t)row * HID;
    __shared__ float s1[256], s2[256];
    float ss = 0.f, am = 0.f, xv[8];
#pragma unroll
    for (int k = 0; k < 8; k++) {
        float v = xr[tid + k * 256];
        xv[k] = v; ss += v * v; am = fmaxf(am, fabsf(v));
    }
    s1[tid] = ss; s2[tid] = am; __syncthreads();
    for (int o = 128; o > 0; o >>= 1) {
        if (tid < o) { s1[tid] += s1[tid + o]; s2[tid] = fmaxf(s2[tid], s2[tid + o]); }
        __syncthreads();
    }
    const float r  = rsqrt_acc(s1[0] * (1.0f / HID) + 1e-8f);
    const float sc = __fdiv_rn(127.0f, fmaxf(s2[0] * r, 1e-5f));
    __half* qr = Q + (size_t)row * HID;
#pragma unroll
    for (int k = 0; k < 8; k++)
        qr[tid + k * 256] = __float2half_rn(fminf(fmaxf(rintf(xv[k] * r * sc), -128.f), 127.f));
    if (tid == 0) dsd[row] = __fdiv_rn(1.0f, sc);
}

// ---------------- RMSNorm + quant (h, I=8192) --------------------------------------
__global__ void k_rq_h(const float* __restrict__ X, __half* __restrict__ Q,
                       float* __restrict__ dsd) {
    const int row = blockIdx.x, tid = threadIdx.x;
    const float* xr = X + (size_t)row * IMD;
    __shared__ float s1[256], s2[256];
    float ss = 0.f, am = 0.f, xv[32];
#pragma unroll
    for (int k = 0; k < 32; k++) {
        float v = xr[tid + k * 256];
        xv[k] = v; ss += v * v; am = fmaxf(am, fabsf(v));
    }
    s1[tid] = ss; s2[tid] = am; __syncthreads();
    for (int o = 128; o > 0; o >>= 1) {
        if (tid < o) { s1[tid] += s1[tid + o]; s2[tid] = fmaxf(s2[tid], s2[tid + o]); }
        __syncthreads();
    }
    const float r  = rsqrt_acc(s1[0] * (1.0f / IMD) + 1e-8f);
    const float sc = __fdiv_rn(127.0f, fmaxf(s2[0] * r, 1e-5f));
    __half* qr = Q + (size_t)row * IMD;
#pragma unroll
    for (int k = 0; k < 32; k++)
        qr[tid + k * 256] = __float2half_rn(fminf(fmaxf(rintf(xv[k] * r * sc), -128.f), 127.f));
    if (tid == 0) dsd[row] = __fdiv_rn(1.0f, sc);
}

// ---------------- fp16 HMMA GEMM (exact integer math) -------------------------------
// CTA tile 128x64, K-tile 64, 4-stage cp.async, 256 threads / 8 warps (4m x 2n),
// warp tile 32x32 -> ~100 regs => TWO CTAs per SM (independent barrier domains).
// Pipeline invariant: 3 prologue commits -> consume-wait is wait_group 2.
// GATED: B rows interleaved (gate,v) -> epilogue silu(g)*v, output width N/2.
static const int ASTG = 128 * 128;          // 16KB per stage (A)
static const int BSTG = 64 * 128;           // 8KB  per stage (B)
static const int STG  = ASTG + BSTG;        // 24KB
static const int GSMEM = 4 * STG + 256;     // 4 stages

template<bool GATED>
__global__ void __launch_bounds__(256, 2)
k_gemm_hmma(const __half* __restrict__ A, const __half* __restrict__ B,
            float* __restrict__ C, const float* __restrict__ rds,
            const unsigned long long* __restrict__ acc, double inv_n, int K, int ldC) {
    extern __shared__ char dsm[];
    const uint32_t base = (s2u(dsm) + 127u) & ~127u;
    const int tid  = threadIdx.x;
    const int lane = tid & 31;
    const int warp = tid >> 5;
    const int wm = warp >> 1;          // 0..3 (m groups of 32)
    const int wn = warp & 1;           // 0..1 (n groups of 32)
    const int rowA = blockIdx.y << 7;  // 128 M rows
    const int rowB = blockIdx.x << 6;  // 64  N rows
    const int KT = K >> 6;

    // loaders: A: row=tid>>1 (128 rows), 4 chunks; B: row=tid>>2 (64 rows), 2 chunks
    const int arw = tid >> 1, acb = (tid & 1) << 2;
    const int brw = tid >> 2, bcb = (tid & 3) << 1;
    const char* gsa = (const char*)(A + (size_t)(rowA + arw) * K) + acb * 16;
    const char* gsb = (const char*)(B + (size_t)(rowB + brw) * K) + bcb * 16;
    uint32_t dA[4], dB[2];
#pragma unroll
    for (int c = 0; c < 4; c++) dA[c] = base + SWZ((uint32_t)(arw * 128 + (acb + c) * 16));
#pragma unroll
    for (int c = 0; c < 2; c++) dB[c] = base + ASTG + SWZ((uint32_t)(brw * 128 + (bcb + c) * 16));

#define LD_STAGE(j) do { \
    const uint32_t off = ((j) & 3) * STG; \
    const char* pa = gsa + (size_t)(j) * 128; \
    const char* pb = gsb + (size_t)(j) * 128; \
    _Pragma("unroll") for (int c = 0; c < 4; c++) cp16(dA[c] + off, pa + c * 16); \
    _Pragma("unroll") for (int c = 0; c < 2; c++) cp16(dB[c] + off, pb + c * 16); \
} while (0)

    float fa[2][4][4];
#pragma unroll
    for (int i = 0; i < 2; i++)
#pragma unroll
        for (int j = 0; j < 4; j++)
#pragma unroll
            for (int k = 0; k < 4; k++) fa[i][j][k] = 0.f;

    LD_STAGE(0); asm volatile("cp.async.commit_group;");
    LD_STAGE(1); asm volatile("cp.async.commit_group;");
    LD_STAGE(2); asm volatile("cp.async.commit_group;");

    // ldmatrix per-lane address components
    const int arow = lane & 15;          // A: + wm*32 + ms*16
    const int achk = lane >> 4;          // A: + ks*2
    const int brow = lane & 7;           // B: + wn*32 + ns*8
    const int bchk = lane >> 3;          // B: + kp*4

    for (int j = 0; j < KT; j++) {
        asm volatile("cp.async.wait_group 2;");   // stage j complete (3 prologue commits)
        __syncthreads();
        if (j + 3 < KT) LD_STAGE(j + 3);
        asm volatile("cp.async.commit_group;");

        const uint32_t aB = base + (j & 3) * STG;
        const uint32_t bB = aB + ASTG;
#pragma unroll
        for (int kp = 0; kp < 2; kp++) {
            uint32_t bfr[4][4];
#pragma unroll
            for (int ns = 0; ns < 4; ns++)
                ldsm4(bfr[ns], bB + SWZ((uint32_t)((wn * 32 + ns * 8 + brow) * 128 +
                                                   (kp * 4 + bchk) * 16)));
#pragma unroll
            for (int kk = 0; kk < 2; kk++) {
                const int ks = kp * 2 + kk;
#pragma unroll
                for (int ms = 0; ms < 2; ms++) {
                    uint32_t afr[4];
                    ldsm4(afr, aB + SWZ((uint32_t)((wm * 32 + ms * 16 + arow) * 128 +
                                                   (ks * 2 + achk) * 16)));
#pragma unroll
                    for (int ns = 0; ns < 4; ns++)
                        mma_f16(fa[ms][ns], afr, &bfr[ns][kk * 2]);
                }
            }
        }
    }

    // ---------------- epilogue ----------------
    const float wmv = wm_from(acc, inv_n);
#pragma unroll
    for (int ms = 0; ms < 2; ms++) {
        const int r0 = rowA + wm * 32 + ms * 16 + (lane >> 2);
        const float ds0 = rds[r0] * wmv;
        const float ds1 = rds[r0 + 8] * wmv;
        if (GATED) {
#pragma unroll
            for (int ns = 0; ns < 4; ns++) {
                const int col = (rowB >> 1) + wn * 16 + ns * 4 + (lane & 3);
                float g0 = fa[ms][ns][0] * ds0;
                float v0 = fa[ms][ns][1] * ds0;
                float g1 = fa[ms][ns][2] * ds1;
                float v1 = fa[ms][ns][3] * ds1;
                C[(size_t)r0 * ldC + col]       = g0 * v0 * __fdiv_rn(1.0f, 1.0f + expf(-g0));
                C[(size_t)(r0 + 8) * ldC + col] = g1 * v1 * __fdiv_rn(1.0f, 1.0f + expf(-g1));
            }
        } else {
#pragma unroll
            for (int ns = 0; ns < 4; ns++) {
                const int col = rowB + wn * 32 + ns * 8 + ((lane & 3) << 1);
                float2 lo = make_float2(fa[ms][ns][0] * ds0, fa[ms][ns][1] * ds0);
                float2 hi = make_float2(fa[ms][ns][2] * ds1, fa[ms][ns][3] * ds1);
                *(float2*)(C + (size_t)r0 * ldC + col)       = lo;
                *(float2*)(C + (size_t)(r0 + 8) * ldC + col) = hi;
            }
        }
    }
}

// ---------------- launch --------------------------------------------------------
// GEMM1 sits at my launch index 3 (ncu -s 5 -c 1 catches it).
extern "C" void kernel_launch(void* const* d_in, const int* in_sizes, int n_in,
                              void* d_out, int out_size) {
    const float* x  = (const float*)d_in[0];
    const float* wg = (const float*)d_in[1];
    const float* wd = (const float*)d_in[2];
    float* out = (float*)d_out;

    void *p_wgq, *p_wdq, *p_xq, *p_hq, *p_xds, *p_hds, *p_h, *p_acc;
    cudaGetSymbolAddress(&p_wgq, g_wgq);
    cudaGetSymbolAddress(&p_wdq, g_wdq);
    cudaGetSymbolAddress(&p_xq,  g_xq);
    cudaGetSymbolAddress(&p_hq,  g_hq);
    cudaGetSymbolAddress(&p_xds, g_xds);
    cudaGetSymbolAddress(&p_hds, g_hds);
    cudaGetSymbolAddress(&p_h,   g_h);
    cudaGetSymbolAddress(&p_acc, g_acc);
    unsigned long long* acc0 = (unsigned long long*)p_acc;
    unsigned long long* acc1 = acc0 + 1;
    const double INV_WG = 1.0 / 33554432.0;
    const double INV_WD = 1.0 / 16777216.0;

    cudaFuncSetAttribute(k_gemm_hmma<true>,  cudaFuncAttributeMaxDynamicSharedMemorySize, GSMEM);
    cudaFuncSetAttribute(k_gemm_hmma<false>, cudaFuncAttributeMaxDynamicSharedMemorySize, GSMEM);

    // [0] RMSNorm + quant x (also zeroes accumulators)
    k_rq_x<<<T_TOK, 256>>>(x, (__half*)p_xq, (float*)p_xds, acc0);
    // [1] w_gate |w| fixed-point sum
    k_absum_u64<<<2048, 256>>>(wg, acc0);
    // [2] quantize w_gate (row-interleaved, fp16)
    k_quant_wg<<<8388608 / 256, 256>>>((const float4*)wg, (__half2*)p_wgq, acc0, INV_WG, 8388608);
    // [3] GEMM1 (gated): h[8192,8192] = silu(g)*v        <-- ncu capture target
    k_gemm_hmma<true><<<dim3(N1 / 64, T_TOK / 128), 256, GSMEM>>>(
        (const __half*)p_xq, (const __half*)p_wgq, (float*)p_h,
        (const float*)p_xds, acc0, INV_WG, HID, IMD);
    // [4] w_down |w| fixed-point sum
    k_absum_u64<<<1024, 256>>>(wd, acc1);
    // [5] quantize w_down
    k_quant_w<<<4194304 / 256, 256>>>((const float4*)wd, (__half2*)p_wdq, acc1, INV_WD, 4194304);
    // [6] RMSNorm + quant h
    k_rq_h<<<T_TOK, 256>>>((const float*)p_h, (__half*)p_hq, (float*)p_hds);
    // [7] GEMM2: out[8192,2048]
    k_gemm_hmma<false><<<dim3(HID / 64, T_TOK / 128), 256, GSMEM>>>(
        (const __half*)p_hq, (const __half*)p_wdq, out,
        (const float*)p_hds, acc1, INV_WD, IMD, HID);
}